// round 1
// baseline (speedup 1.0000x reference)
#include <cuda_runtime.h>
#include <math.h>

#define BB  2
#define NN  8192
#define MM  4096
#define CC  64
#define KK  15      // K-1 neighbors actually used
#define HH  256

// Scratch (allocation-free rule: __device__ globals)
__device__ int g_close_idx[BB * NN];
__device__ int g_knn[BB * MM * KK];

// ---------------------------------------------------------------------------
// Kernel A: nearest clean point for each noisy point (argmin over M)
// 128 threads/block, one query per thread. Candidates tiled through smem,
// packed float4 reads (3 float4 = 4 points). All threads scan the same j ->
// smem broadcast, conflict-free.
// ---------------------------------------------------------------------------
__global__ __launch_bounds__(128) void nn_kernel(
    const float* __restrict__ pcl, const float* __restrict__ pcl_noise)
{
    const int b = blockIdx.y;
    const int n = blockIdx.x * 128 + threadIdx.x;
    const float* pb = pcl + (size_t)b * MM * 3;

    const float qx = pcl_noise[((size_t)b * NN + n) * 3 + 0];
    const float qy = pcl_noise[((size_t)b * NN + n) * 3 + 1];
    const float qz = pcl_noise[((size_t)b * NN + n) * 3 + 2];

    __shared__ float sp[3 * 1024];

    float best = 3.4e38f;
    int   bi   = 0;

    for (int t0 = 0; t0 < MM; t0 += 1024) {
        for (int i = threadIdx.x; i < 3072; i += 128)
            sp[i] = pb[t0 * 3 + i];
        __syncthreads();

        const float4* sp4 = (const float4*)sp;
        #pragma unroll 4
        for (int j = 0; j < 1024; j += 4) {
            const int f4 = (j * 3) >> 2;
            float4 a = sp4[f4], c1 = sp4[f4 + 1], c2 = sp4[f4 + 2];
            float dx, dy, dz;
            dx = a.x - qx;  dy = a.y - qy;  dz = a.z - qz;
            float d0 = dx * dx + dy * dy + dz * dz;
            dx = a.w - qx;  dy = c1.x - qy; dz = c1.y - qz;
            float d1 = dx * dx + dy * dy + dz * dz;
            dx = c1.z - qx; dy = c1.w - qy; dz = c2.x - qz;
            float d2 = dx * dx + dy * dy + dz * dz;
            dx = c2.y - qx; dy = c2.z - qz + (qz - qy); // placeholder avoided below
            // (recompute cleanly to avoid any confusion)
            dy = c2.z - qy; dz = c2.w - qz;
            float d3 = dx * dx + dy * dy + dz * dz;

            if (d0 < best) { best = d0; bi = t0 + j;     }
            if (d1 < best) { best = d1; bi = t0 + j + 1; }
            if (d2 < best) { best = d2; bi = t0 + j + 2; }
            if (d3 < best) { best = d3; bi = t0 + j + 3; }
        }
        __syncthreads();
    }
    g_close_idx[b * NN + n] = bi;
}

// ---------------------------------------------------------------------------
// Kernel B: self-KNN table of pcl (top-16 incl. self; store ranks 1..15).
// Register-guarded (dmax) insertion sort into local top-16.
// Stable tie-break: strict '>' shift => equal dists keep lower index first.
// ---------------------------------------------------------------------------
__global__ __launch_bounds__(128) void knn_kernel(const float* __restrict__ pcl)
{
    const int b = blockIdx.y;
    const int m = blockIdx.x * 128 + threadIdx.x;
    const float* pb = pcl + (size_t)b * MM * 3;

    const float qx = pb[m * 3 + 0];
    const float qy = pb[m * 3 + 1];
    const float qz = pb[m * 3 + 2];

    float dl[16];
    int   il[16];
    #pragma unroll
    for (int i = 0; i < 16; i++) { dl[i] = 3.4e38f; il[i] = 0; }
    float dmax = 3.4e38f;

    __shared__ float sp[3 * 1024];

    for (int t0 = 0; t0 < MM; t0 += 1024) {
        for (int i = threadIdx.x; i < 3072; i += 128)
            sp[i] = pb[t0 * 3 + i];
        __syncthreads();

        const float4* sp4 = (const float4*)sp;
        for (int j = 0; j < 1024; j += 4) {
            const int f4 = (j * 3) >> 2;
            float4 a = sp4[f4], c1 = sp4[f4 + 1], c2 = sp4[f4 + 2];
            float px[4], py[4], pz[4];
            px[0] = a.x;  py[0] = a.y;  pz[0] = a.z;
            px[1] = a.w;  py[1] = c1.x; pz[1] = c1.y;
            px[2] = c1.z; py[2] = c1.w; pz[2] = c2.x;
            px[3] = c2.y; py[3] = c2.z; pz[3] = c2.w;
            #pragma unroll
            for (int r = 0; r < 4; r++) {
                float dx = px[r] - qx, dy = py[r] - qy, dz = pz[r] - qz;
                float dc = dx * dx + dy * dy + dz * dz;
                if (dc < dmax) {
                    int jc = t0 + j + r;
                    int p = 15;
                    while (p > 0 && dl[p - 1] > dc) {
                        dl[p] = dl[p - 1]; il[p] = il[p - 1]; --p;
                    }
                    dl[p] = dc; il[p] = jc;
                    dmax = dl[15];
                }
            }
        }
        __syncthreads();
    }

    int base = (b * MM + m) * KK;
    #pragma unroll
    for (int t = 0; t < KK; t++) g_knn[base + t] = il[t + 1];
}

// ---------------------------------------------------------------------------
// Kernel C: fused gather + weights + MLP2 (with weighted-sum pushed before
// the second linear layer) + co/close features + final MLP. One warp/point.
// ---------------------------------------------------------------------------
__global__ __launch_bounds__(128) void fused_kernel(
    const float* __restrict__ pcl,  const float* __restrict__ pcl_noise,
    const float* __restrict__ feature,
    const float* __restrict__ w2a,  const float* __restrict__ b2a,
    const float* __restrict__ g2a,  const float* __restrict__ bt2a,
    const float* __restrict__ w2b,  const float* __restrict__ b2b,
    const float* __restrict__ w1a,  const float* __restrict__ b1a,
    const float* __restrict__ g1a,  const float* __restrict__ bt1a,
    const float* __restrict__ w1b,  const float* __restrict__ b1b,
    float* __restrict__ out)
{
    const int wrp  = threadIdx.x >> 5;
    const int lane = threadIdx.x & 31;
    const int pt   = blockIdx.x * 4 + wrp;       // 0 .. B*N-1
    const int b    = pt >> 13;                   // / 8192
    const int n    = pt & (NN - 1);

    __shared__ float s_hbar[4][HH];
    __shared__ float s_df[4][3 * CC];
    __shared__ float s_h1[4][CC];

    const float invs = rsqrtf(1.0f + 1e-5f);
    const unsigned FULL = 0xffffffffu;

    const int ci = g_close_idx[b * NN + n];
    const float qx = pcl_noise[((size_t)b * NN + n) * 3 + 0];
    const float qy = pcl_noise[((size_t)b * NN + n) * 3 + 1];
    const float qz = pcl_noise[((size_t)b * NN + n) * 3 + 2];
    const float cpx = pcl[((size_t)b * MM + ci) * 3 + 0];
    const float cpy = pcl[((size_t)b * MM + ci) * 3 + 1];
    const float cpz = pcl[((size_t)b * MM + ci) * 3 + 2];

    // lane k (<15) owns neighbor k
    int jk = 0; float ldx = 0.f, ldy = 0.f, ldz = 0.f, e = 0.f;
    if (lane < KK) {
        jk = g_knn[(b * MM + ci) * KK + lane];
        float px = pcl[((size_t)b * MM + jk) * 3 + 0];
        float py = pcl[((size_t)b * MM + jk) * 3 + 1];
        float pz = pcl[((size_t)b * MM + jk) * 3 + 2];
        ldx = px - qx; ldy = py - qy; ldz = pz - qz;
        float dst = sqrtf(ldx * ldx + ldy * ldy + ldz * ldz);
        e = expf(-10.0f * dst);
    }
    float S = e;
    #pragma unroll
    for (int o = 16; o; o >>= 1) S += __shfl_xor_sync(FULL, S, o);
    const float denom = S + 1e-7f;
    const float lw    = e / denom;      // this lane's weight (0 for lane>=15)
    const float ssum  = S / denom;      // sum of weights

    // ----- layer 1 (6 -> 256, BN+ReLU), weighted-summed over k into hbar ----
    // channels c = lane + 32*i, i = 0..7
    float a0[8], a1[8], a2[8], t[8], gsv[8], btv[8], hb[8];
    #pragma unroll
    for (int i = 0; i < 8; i++) {
        const int c = lane + 32 * i;
        a0[i] = w2a[c * 6 + 0]; a1[i] = w2a[c * 6 + 1]; a2[i] = w2a[c * 6 + 2];
        const float a3 = w2a[c * 6 + 3], a4 = w2a[c * 6 + 4], a5 = w2a[c * 6 + 5];
        t[i]   = a3 * cpx + a4 * cpy + a5 * cpz + b2a[c];
        gsv[i] = g2a[c] * invs;
        btv[i] = bt2a[c];
        hb[i]  = 0.f;
    }
    #pragma unroll
    for (int k = 0; k < KK; k++) {
        const float kdx = __shfl_sync(FULL, ldx, k);
        const float kdy = __shfl_sync(FULL, ldy, k);
        const float kdz = __shfl_sync(FULL, ldz, k);
        const float kw  = __shfl_sync(FULL, lw,  k);
        #pragma unroll
        for (int i = 0; i < 8; i++) {
            float pre = a0[i] * kdx + a1[i] * kdy + a2[i] * kdz + t[i];
            float hbn = pre * gsv[i] + btv[i];
            hb[i] += kw * fmaxf(hbn, 0.f);
        }
    }
    #pragma unroll
    for (int i = 0; i < 8; i++) s_hbar[wrp][lane + 32 * i] = hb[i];
    __syncwarp();

    // ----- layer 2: point_feature = w2b @ hbar + b2b * ssum ------------------
    const int o1 = lane, o2 = lane + 32;
    float pf1 = 0.f, pf2 = 0.f;
    {
        const float4* h4 = (const float4*)s_hbar[wrp];
        const float4* wa = (const float4*)(w2b + (size_t)o1 * HH);
        const float4* wb = (const float4*)(w2b + (size_t)o2 * HH);
        #pragma unroll
        for (int c4 = 0; c4 < HH / 4; c4++) {
            float4 h = h4[c4], x = wa[c4], y = wb[c4];
            pf1 += h.x * x.x + h.y * x.y + h.z * x.z + h.w * x.w;
            pf2 += h.x * y.x + h.y * y.y + h.z * y.z + h.w * y.w;
        }
    }
    pf1 += b2b[o1] * ssum;
    pf2 += b2b[o2] * ssum;

    // ----- close_feat + co_feature ------------------------------------------
    const float cf1 = feature[((size_t)b * MM + ci) * CC + o1];
    const float cf2 = feature[((size_t)b * MM + ci) * CC + o2];
    float co1 = 0.f, co2 = 0.f;
    #pragma unroll
    for (int k = 0; k < KK; k++) {
        const int   j  = __shfl_sync(FULL, jk, k);
        const float kw = __shfl_sync(FULL, lw, k);
        co1 += kw * feature[((size_t)b * MM + j) * CC + o1];
        co2 += kw * feature[((size_t)b * MM + j) * CC + o2];
    }
    s_df[wrp][o1] = cf1;        s_df[wrp][o2] = cf2;
    s_df[wrp][CC + o1] = co1;   s_df[wrp][CC + o2] = co2;
    s_df[wrp][2 * CC + o1] = pf1; s_df[wrp][2 * CC + o2] = pf2;
    __syncwarp();

    // ----- final MLP: 192 -> 64 (BN+ReLU) -> 64 -----------------------------
    float acc1 = 0.f, acc2 = 0.f;
    {
        const float4* d4 = (const float4*)s_df[wrp];
        const float4* wa = (const float4*)(w1a + (size_t)o1 * (3 * CC));
        const float4* wb = (const float4*)(w1a + (size_t)o2 * (3 * CC));
        #pragma unroll
        for (int c4 = 0; c4 < (3 * CC) / 4; c4++) {
            float4 d = d4[c4], x = wa[c4], y = wb[c4];
            acc1 += d.x * x.x + d.y * x.y + d.z * x.z + d.w * x.w;
            acc2 += d.x * y.x + d.y * y.y + d.z * y.z + d.w * y.w;
        }
    }
    const float h1a = fmaxf((acc1 + b1a[o1]) * (g1a[o1] * invs) + bt1a[o1], 0.f);
    const float h1b = fmaxf((acc2 + b1a[o2]) * (g1a[o2] * invs) + bt1a[o2], 0.f);
    s_h1[wrp][o1] = h1a; s_h1[wrp][o2] = h1b;
    __syncwarp();

    float r1 = b1b[o1], r2 = b1b[o2];
    {
        const float4* h4 = (const float4*)s_h1[wrp];
        const float4* wa = (const float4*)(w1b + (size_t)o1 * CC);
        const float4* wb = (const float4*)(w1b + (size_t)o2 * CC);
        #pragma unroll
        for (int c4 = 0; c4 < CC / 4; c4++) {
            float4 h = h4[c4], x = wa[c4], y = wb[c4];
            r1 += h.x * x.x + h.y * x.y + h.z * x.z + h.w * x.w;
            r2 += h.x * y.x + h.y * y.y + h.z * y.z + h.w * y.w;
        }
    }
    out[((size_t)b * NN + n) * CC + o1] = r1;
    out[((size_t)b * NN + n) * CC + o2] = r2;
}

// ---------------------------------------------------------------------------
extern "C" void kernel_launch(void* const* d_in, const int* in_sizes, int n_in,
                              void* d_out, int out_size)
{
    (void)in_sizes; (void)n_in; (void)out_size;
    const float* pcl       = (const float*)d_in[0];
    const float* pcl_noise = (const float*)d_in[1];
    const float* feature   = (const float*)d_in[2];
    const float* w2a  = (const float*)d_in[3];
    const float* b2a  = (const float*)d_in[4];
    const float* g2a  = (const float*)d_in[5];
    const float* bt2a = (const float*)d_in[6];
    const float* w2b  = (const float*)d_in[7];
    const float* b2b  = (const float*)d_in[8];
    const float* w1a  = (const float*)d_in[9];
    const float* b1a  = (const float*)d_in[10];
    const float* g1a  = (const float*)d_in[11];
    const float* bt1a = (const float*)d_in[12];
    const float* w1b  = (const float*)d_in[13];
    const float* b1b  = (const float*)d_in[14];
    float* out = (float*)d_out;

    nn_kernel<<<dim3(NN / 128, BB), 128>>>(pcl, pcl_noise);
    knn_kernel<<<dim3(MM / 128, BB), 128>>>(pcl);
    fused_kernel<<<(BB * NN) / 4, 128>>>(
        pcl, pcl_noise, feature,
        w2a, b2a, g2a, bt2a, w2b, b2b,
        w1a, b1a, g1a, bt1a, w1b, b1b, out);
}

// round 2
// speedup vs baseline: 1.5032x; 1.5032x over previous
#include <cuda_runtime.h>
#include <math.h>

#define BB  2
#define NN  8192
#define MM  4096
#define CC  64
#define KK  15      // K-1 neighbors actually used
#define HH  256
#define NCHUNK 4
#define CHM (MM / NCHUNK)   // 1024

// Scratch (allocation-free rule: __device__ globals)
__device__ unsigned long long g_nn_part[BB * NCHUNK * NN];
__device__ int g_knn[BB * MM * KK];

static __device__ __forceinline__ unsigned long long packkey(float d, int idx) {
    return ((unsigned long long)__float_as_uint(d) << 32) | (unsigned)idx;
}

// ---------------------------------------------------------------------------
// Kernel A: partial argmin over a 1024-candidate chunk of pcl, per noisy pt.
// grid (NN/128, NCHUNK, BB); one thread per query, chunk tiled in smem,
// broadcast reads (all threads scan same j).
// ---------------------------------------------------------------------------
__global__ __launch_bounds__(128) void nn_part_kernel(
    const float* __restrict__ pcl, const float* __restrict__ pcl_noise)
{
    const int b = blockIdx.z;
    const int chunk = blockIdx.y;
    const int n = blockIdx.x * 128 + threadIdx.x;
    const float* pb = pcl + (size_t)b * MM * 3 + (size_t)chunk * CHM * 3;

    const float qx = pcl_noise[((size_t)b * NN + n) * 3 + 0];
    const float qy = pcl_noise[((size_t)b * NN + n) * 3 + 1];
    const float qz = pcl_noise[((size_t)b * NN + n) * 3 + 2];

    __shared__ float sp[3 * CHM];
    for (int i = threadIdx.x; i < (3 * CHM) / 4; i += 128)
        ((float4*)sp)[i] = ((const float4*)pb)[i];
    __syncthreads();

    float best = 3.4e38f;
    int   bi   = 0;

    const float4* sp4 = (const float4*)sp;
    #pragma unroll 4
    for (int j = 0; j < CHM; j += 4) {
        const int f4 = (j * 3) >> 2;
        float4 a = sp4[f4], c1 = sp4[f4 + 1], c2 = sp4[f4 + 2];
        float dx, dy, dz;
        dx = a.x - qx;  dy = a.y - qy;  dz = a.z - qz;
        float d0 = dx * dx + dy * dy + dz * dz;
        dx = a.w - qx;  dy = c1.x - qy; dz = c1.y - qz;
        float d1 = dx * dx + dy * dy + dz * dz;
        dx = c1.z - qx; dy = c1.w - qy; dz = c2.x - qz;
        float d2 = dx * dx + dy * dy + dz * dz;
        dx = c2.y - qx; dy = c2.z - qy; dz = c2.w - qz;
        float d3 = dx * dx + dy * dy + dz * dz;

        if (d0 < best) { best = d0; bi = j;     }
        if (d1 < best) { best = d1; bi = j + 1; }
        if (d2 < best) { best = d2; bi = j + 2; }
        if (d3 < best) { best = d3; bi = j + 3; }
    }
    g_nn_part[((size_t)b * NCHUNK + chunk) * NN + n] =
        packkey(best, chunk * CHM + bi);
}

// ---------------------------------------------------------------------------
// Kernel B: self-KNN of pcl, warp-per-query. SoA smem tile of all M points.
// Lane scans j = lane + 32*t (conflict-free), keeps register top-16 via
// fully-unrolled bubble-insert (stable: strict '<' swap). Cross-lane merge
// via 16 rounds of u64 (dist,idx) warp-min — exact top_k tie semantics.
// grid (MM/16, BB), 128 threads = 4 warps, 4 queries per warp.
// ---------------------------------------------------------------------------
__global__ __launch_bounds__(128) void knn_kernel(const float* __restrict__ pcl)
{
    const int b = blockIdx.y;
    const int wrp  = threadIdx.x >> 5;
    const int lane = threadIdx.x & 31;
    const float* pb = pcl + (size_t)b * MM * 3;
    const unsigned FULL = 0xffffffffu;

    __shared__ float sx[MM], sy[MM], sz[MM];
    for (int i = threadIdx.x; i < 3 * MM; i += 128) {
        float v = pb[i];
        int m = i / 3, c = i - 3 * m;
        if (c == 0) sx[m] = v; else if (c == 1) sy[m] = v; else sz[m] = v;
    }
    __syncthreads();

    for (int q = 0; q < 4; q++) {
        const int m = blockIdx.x * 16 + wrp * 4 + q;
        const float qx = sx[m], qy = sy[m], qz = sz[m];

        float dl[16];
        int   il[16];
        #pragma unroll
        for (int i = 0; i < 16; i++) { dl[i] = 3.4e38f; il[i] = 0; }

        #pragma unroll 4
        for (int t = 0; t < MM / 32; t++) {
            const int j = lane + 32 * t;
            float dx = sx[j] - qx, dy = sy[j] - qy, dz = sz[j] - qz;
            float dc = dx * dx + dy * dy + dz * dz;
            if (dc < dl[15]) {
                dl[15] = dc; il[15] = j;
                #pragma unroll
                for (int i = 15; i > 0; i--) {
                    if (dl[i] < dl[i - 1]) {
                        float td = dl[i]; dl[i] = dl[i - 1]; dl[i - 1] = td;
                        int   ti = il[i]; il[i] = il[i - 1]; il[i - 1] = ti;
                    }
                }
            }
        }

        // cross-lane merge: 16 selection rounds (round 0 = self point, dropped)
        unsigned long long key = packkey(dl[0], il[0]);
        const int base = (b * MM + m) * KK;
        #pragma unroll
        for (int r = 0; r < 16; r++) {
            unsigned long long kmin = key;
            #pragma unroll
            for (int o = 16; o; o >>= 1) {
                unsigned long long other = __shfl_xor_sync(FULL, kmin, o);
                if (other < kmin) kmin = other;
            }
            if (r > 0 && lane == 0)
                g_knn[base + r - 1] = (int)(kmin & 0xffffffffu);
            if (key == kmin) {
                // pop head: shift register list down
                #pragma unroll
                for (int i = 0; i < 15; i++) { dl[i] = dl[i + 1]; il[i] = il[i + 1]; }
                dl[15] = 3.4e38f; il[15] = 0;
                key = packkey(dl[0], il[0]);
            }
        }
    }
}

// ---------------------------------------------------------------------------
// Kernel C: fused NN-merge + gather + weights + MLP2 (weighted-sum pushed
// before second linear) + co/close features + final MLP. One warp per point.
// ---------------------------------------------------------------------------
__global__ __launch_bounds__(128) void fused_kernel(
    const float* __restrict__ pcl,  const float* __restrict__ pcl_noise,
    const float* __restrict__ feature,
    const float* __restrict__ w2a,  const float* __restrict__ b2a,
    const float* __restrict__ g2a,  const float* __restrict__ bt2a,
    const float* __restrict__ w2b,  const float* __restrict__ b2b,
    const float* __restrict__ w1a,  const float* __restrict__ b1a,
    const float* __restrict__ g1a,  const float* __restrict__ bt1a,
    const float* __restrict__ w1b,  const float* __restrict__ b1b,
    float* __restrict__ out)
{
    const int wrp  = threadIdx.x >> 5;
    const int lane = threadIdx.x & 31;
    const int pt   = blockIdx.x * 4 + wrp;       // 0 .. B*N-1
    const int b    = pt >> 13;                   // / 8192
    const int n    = pt & (NN - 1);

    __shared__ float s_hbar[4][HH];
    __shared__ float s_df[4][3 * CC];
    __shared__ float s_h1[4][CC];

    const float invs = rsqrtf(1.0f + 1e-5f);
    const unsigned FULL = 0xffffffffu;

    // merge partial NN keys
    unsigned long long kmin = 0xffffffffffffffffull;
    #pragma unroll
    for (int c = 0; c < NCHUNK; c++) {
        unsigned long long k = g_nn_part[((size_t)b * NCHUNK + c) * NN + n];
        if (k < kmin) kmin = k;
    }
    const int ci = (int)(kmin & 0xffffffffu);

    const float qx = pcl_noise[((size_t)b * NN + n) * 3 + 0];
    const float qy = pcl_noise[((size_t)b * NN + n) * 3 + 1];
    const float qz = pcl_noise[((size_t)b * NN + n) * 3 + 2];
    const float cpx = pcl[((size_t)b * MM + ci) * 3 + 0];
    const float cpy = pcl[((size_t)b * MM + ci) * 3 + 1];
    const float cpz = pcl[((size_t)b * MM + ci) * 3 + 2];

    // lane k (<15) owns neighbor k
    int jk = 0; float ldx = 0.f, ldy = 0.f, ldz = 0.f, e = 0.f;
    if (lane < KK) {
        jk = g_knn[(b * MM + ci) * KK + lane];
        float px = pcl[((size_t)b * MM + jk) * 3 + 0];
        float py = pcl[((size_t)b * MM + jk) * 3 + 1];
        float pz = pcl[((size_t)b * MM + jk) * 3 + 2];
        ldx = px - qx; ldy = py - qy; ldz = pz - qz;
        float dst = sqrtf(ldx * ldx + ldy * ldy + ldz * ldz);
        e = expf(-10.0f * dst);
    }
    float S = e;
    #pragma unroll
    for (int o = 16; o; o >>= 1) S += __shfl_xor_sync(FULL, S, o);
    const float denom = S + 1e-7f;
    const float lw    = e / denom;      // this lane's weight (0 for lane>=15)
    const float ssum  = S / denom;      // sum of weights

    // ----- layer 1 (6 -> 256, BN+ReLU), weighted-summed over k into hbar ----
    float a0[8], a1[8], a2[8], t[8], gsv[8], btv[8], hb[8];
    #pragma unroll
    for (int i = 0; i < 8; i++) {
        const int c = lane + 32 * i;
        a0[i] = w2a[c * 6 + 0]; a1[i] = w2a[c * 6 + 1]; a2[i] = w2a[c * 6 + 2];
        const float a3 = w2a[c * 6 + 3], a4 = w2a[c * 6 + 4], a5 = w2a[c * 6 + 5];
        t[i]   = a3 * cpx + a4 * cpy + a5 * cpz + b2a[c];
        gsv[i] = g2a[c] * invs;
        btv[i] = bt2a[c];
        hb[i]  = 0.f;
    }
    #pragma unroll
    for (int k = 0; k < KK; k++) {
        const float kdx = __shfl_sync(FULL, ldx, k);
        const float kdy = __shfl_sync(FULL, ldy, k);
        const float kdz = __shfl_sync(FULL, ldz, k);
        const float kw  = __shfl_sync(FULL, lw,  k);
        #pragma unroll
        for (int i = 0; i < 8; i++) {
            float pre = a0[i] * kdx + a1[i] * kdy + a2[i] * kdz + t[i];
            float hbn = pre * gsv[i] + btv[i];
            hb[i] += kw * fmaxf(hbn, 0.f);
        }
    }
    #pragma unroll
    for (int i = 0; i < 8; i++) s_hbar[wrp][lane + 32 * i] = hb[i];
    __syncwarp();

    // ----- layer 2: point_feature = w2b @ hbar + b2b * ssum ------------------
    const int o1 = lane, o2 = lane + 32;
    float pf1 = 0.f, pf2 = 0.f;
    {
        const float4* h4 = (const float4*)s_hbar[wrp];
        const float4* wa = (const float4*)(w2b + (size_t)o1 * HH);
        const float4* wb = (const float4*)(w2b + (size_t)o2 * HH);
        #pragma unroll
        for (int c4 = 0; c4 < HH / 4; c4++) {
            float4 h = h4[c4], x = wa[c4], y = wb[c4];
            pf1 += h.x * x.x + h.y * x.y + h.z * x.z + h.w * x.w;
            pf2 += h.x * y.x + h.y * y.y + h.z * y.z + h.w * y.w;
        }
    }
    pf1 += b2b[o1] * ssum;
    pf2 += b2b[o2] * ssum;

    // ----- close_feat + co_feature ------------------------------------------
    const float cf1 = feature[((size_t)b * MM + ci) * CC + o1];
    const float cf2 = feature[((size_t)b * MM + ci) * CC + o2];
    float co1 = 0.f, co2 = 0.f;
    #pragma unroll
    for (int k = 0; k < KK; k++) {
        const int   j  = __shfl_sync(FULL, jk, k);
        const float kw = __shfl_sync(FULL, lw, k);
        co1 += kw * feature[((size_t)b * MM + j) * CC + o1];
        co2 += kw * feature[((size_t)b * MM + j) * CC + o2];
    }
    s_df[wrp][o1] = cf1;        s_df[wrp][o2] = cf2;
    s_df[wrp][CC + o1] = co1;   s_df[wrp][CC + o2] = co2;
    s_df[wrp][2 * CC + o1] = pf1; s_df[wrp][2 * CC + o2] = pf2;
    __syncwarp();

    // ----- final MLP: 192 -> 64 (BN+ReLU) -> 64 -----------------------------
    float acc1 = 0.f, acc2 = 0.f;
    {
        const float4* d4 = (const float4*)s_df[wrp];
        const float4* wa = (const float4*)(w1a + (size_t)o1 * (3 * CC));
        const float4* wb = (const float4*)(w1a + (size_t)o2 * (3 * CC));
        #pragma unroll
        for (int c4 = 0; c4 < (3 * CC) / 4; c4++) {
            float4 d = d4[c4], x = wa[c4], y = wb[c4];
            acc1 += d.x * x.x + d.y * x.y + d.z * x.z + d.w * x.w;
            acc2 += d.x * y.x + d.y * y.y + d.z * y.z + d.w * y.w;
        }
    }
    const float h1a = fmaxf((acc1 + b1a[o1]) * (g1a[o1] * invs) + bt1a[o1], 0.f);
    const float h1b = fmaxf((acc2 + b1a[o2]) * (g1a[o2] * invs) + bt1a[o2], 0.f);
    s_h1[wrp][o1] = h1a; s_h1[wrp][o2] = h1b;
    __syncwarp();

    float r1 = b1b[o1], r2 = b1b[o2];
    {
        const float4* h4 = (const float4*)s_h1[wrp];
        const float4* wa = (const float4*)(w1b + (size_t)o1 * CC);
        const float4* wb = (const float4*)(w1b + (size_t)o2 * CC);
        #pragma unroll
        for (int c4 = 0; c4 < CC / 4; c4++) {
            float4 h = h4[c4], x = wa[c4], y = wb[c4];
            r1 += h.x * x.x + h.y * x.y + h.z * x.z + h.w * x.w;
            r2 += h.x * y.x + h.y * y.y + h.z * y.z + h.w * y.w;
        }
    }
    out[((size_t)b * NN + n) * CC + o1] = r1;
    out[((size_t)b * NN + n) * CC + o2] = r2;
}

// ---------------------------------------------------------------------------
extern "C" void kernel_launch(void* const* d_in, const int* in_sizes, int n_in,
                              void* d_out, int out_size)
{
    (void)in_sizes; (void)n_in; (void)out_size;
    const float* pcl       = (const float*)d_in[0];
    const float* pcl_noise = (const float*)d_in[1];
    const float* feature   = (const float*)d_in[2];
    const float* w2a  = (const float*)d_in[3];
    const float* b2a  = (const float*)d_in[4];
    const float* g2a  = (const float*)d_in[5];
    const float* bt2a = (const float*)d_in[6];
    const float* w2b  = (const float*)d_in[7];
    const float* b2b  = (const float*)d_in[8];
    const float* w1a  = (const float*)d_in[9];
    const float* b1a  = (const float*)d_in[10];
    const float* g1a  = (const float*)d_in[11];
    const float* bt1a = (const float*)d_in[12];
    const float* w1b  = (const float*)d_in[13];
    const float* b1b  = (const float*)d_in[14];
    float* out = (float*)d_out;

    nn_part_kernel<<<dim3(NN / 128, NCHUNK, BB), 128>>>(pcl, pcl_noise);
    knn_kernel<<<dim3(MM / 16, BB), 128>>>(pcl);
    fused_kernel<<<(BB * NN) / 4, 128>>>(
        pcl, pcl_noise, feature,
        w2a, b2a, g2a, bt2a, w2b, b2b,
        w1a, b1a, g1a, bt1a, w1b, b1b, out);
}

// round 3
// speedup vs baseline: 2.7821x; 1.8508x over previous
#include <cuda_runtime.h>
#include <math.h>

#define BB  2
#define NN  8192
#define MM  4096
#define CC  64
#define KK  15      // K-1 neighbors actually used
#define HH  256
#define NCHUNK 8
#define CHM (MM / NCHUNK)   // 512

// Scratch (allocation-free rule: __device__ globals)
__device__ unsigned long long g_nn_part[BB * NCHUNK * NN];
__device__ int   g_knn[BB * MM * KK];
__device__ float g_wt2b[HH * CC];        // [c][o]
__device__ float g_wt1a[3 * CC * CC];    // [c][o]
__device__ float g_wt1b[CC * CC];        // [c][o]

static __device__ __forceinline__ unsigned long long packkey(float d, int idx) {
    return ((unsigned long long)__float_as_uint(d) << 32) | (unsigned)idx;
}

// ---------------------------------------------------------------------------
// Kernel P: transpose weights into [c][o] layout for coalesced GEMV loads.
// ---------------------------------------------------------------------------
__global__ __launch_bounds__(256) void transpose_kernel(
    const float* __restrict__ w2b, const float* __restrict__ w1a,
    const float* __restrict__ w1b)
{
    const int t = blockIdx.x * 256 + threadIdx.x;
    const int stride = gridDim.x * 256;
    for (int idx = t; idx < HH * CC; idx += stride) {
        int c = idx / CC, o = idx - c * CC;
        g_wt2b[idx] = w2b[o * HH + c];
    }
    for (int idx = t; idx < 3 * CC * CC; idx += stride) {
        int c = idx / CC, o = idx - c * CC;
        g_wt1a[idx] = w1a[o * (3 * CC) + c];
    }
    for (int idx = t; idx < CC * CC; idx += stride) {
        int c = idx / CC, o = idx - c * CC;
        g_wt1b[idx] = w1b[o * CC + c];
    }
}

// ---------------------------------------------------------------------------
// Kernel A: partial argmin over a 512-candidate chunk of pcl, per noisy pt.
// ---------------------------------------------------------------------------
__global__ __launch_bounds__(128) void nn_part_kernel(
    const float* __restrict__ pcl, const float* __restrict__ pcl_noise)
{
    const int b = blockIdx.z;
    const int chunk = blockIdx.y;
    const int n = blockIdx.x * 128 + threadIdx.x;
    const float* pb = pcl + (size_t)b * MM * 3 + (size_t)chunk * CHM * 3;

    const float qx = pcl_noise[((size_t)b * NN + n) * 3 + 0];
    const float qy = pcl_noise[((size_t)b * NN + n) * 3 + 1];
    const float qz = pcl_noise[((size_t)b * NN + n) * 3 + 2];

    __shared__ float sp[3 * CHM];
    for (int i = threadIdx.x; i < (3 * CHM) / 4; i += 128)
        ((float4*)sp)[i] = ((const float4*)pb)[i];
    __syncthreads();

    float best = 3.4e38f;
    int   bi   = 0;

    const float4* sp4 = (const float4*)sp;
    #pragma unroll 4
    for (int j = 0; j < CHM; j += 4) {
        const int f4 = (j * 3) >> 2;
        float4 a = sp4[f4], c1 = sp4[f4 + 1], c2 = sp4[f4 + 2];
        float dx, dy, dz;
        dx = a.x - qx;  dy = a.y - qy;  dz = a.z - qz;
        float d0 = dx * dx + dy * dy + dz * dz;
        dx = a.w - qx;  dy = c1.x - qy; dz = c1.y - qz;
        float d1 = dx * dx + dy * dy + dz * dz;
        dx = c1.z - qx; dy = c1.w - qy; dz = c2.x - qz;
        float d2 = dx * dx + dy * dy + dz * dz;
        dx = c2.y - qx; dy = c2.z - qy; dz = c2.w - qz;
        float d3 = dx * dx + dy * dy + dz * dz;

        if (d0 < best) { best = d0; bi = j;     }
        if (d1 < best) { best = d1; bi = j + 1; }
        if (d2 < best) { best = d2; bi = j + 2; }
        if (d3 < best) { best = d3; bi = j + 3; }
    }
    g_nn_part[((size_t)b * NCHUNK + chunk) * NN + n] =
        packkey(best, chunk * CHM + bi);
}

// ---------------------------------------------------------------------------
// Kernel B: self-KNN of pcl, warp-per-query (register top-16 + warp merge).
// ---------------------------------------------------------------------------
__global__ __launch_bounds__(128) void knn_kernel(const float* __restrict__ pcl)
{
    const int b = blockIdx.y;
    const int wrp  = threadIdx.x >> 5;
    const int lane = threadIdx.x & 31;
    const float* pb = pcl + (size_t)b * MM * 3;
    const unsigned FULL = 0xffffffffu;

    __shared__ float sx[MM], sy[MM], sz[MM];
    for (int i = threadIdx.x; i < 3 * MM; i += 128) {
        float v = pb[i];
        int m = i / 3, c = i - 3 * m;
        if (c == 0) sx[m] = v; else if (c == 1) sy[m] = v; else sz[m] = v;
    }
    __syncthreads();

    for (int q = 0; q < 4; q++) {
        const int m = blockIdx.x * 16 + wrp * 4 + q;
        const float qx = sx[m], qy = sy[m], qz = sz[m];

        float dl[16];
        int   il[16];
        #pragma unroll
        for (int i = 0; i < 16; i++) { dl[i] = 3.4e38f; il[i] = 0; }

        #pragma unroll 4
        for (int t = 0; t < MM / 32; t++) {
            const int j = lane + 32 * t;
            float dx = sx[j] - qx, dy = sy[j] - qy, dz = sz[j] - qz;
            float dc = dx * dx + dy * dy + dz * dz;
            if (dc < dl[15]) {
                dl[15] = dc; il[15] = j;
                #pragma unroll
                for (int i = 15; i > 0; i--) {
                    if (dl[i] < dl[i - 1]) {
                        float td = dl[i]; dl[i] = dl[i - 1]; dl[i - 1] = td;
                        int   ti = il[i]; il[i] = il[i - 1]; il[i - 1] = ti;
                    }
                }
            }
        }

        unsigned long long key = packkey(dl[0], il[0]);
        const int base = (b * MM + m) * KK;
        #pragma unroll
        for (int r = 0; r < 16; r++) {
            unsigned long long kmin = key;
            #pragma unroll
            for (int o = 16; o; o >>= 1) {
                unsigned long long other = __shfl_xor_sync(FULL, kmin, o);
                if (other < kmin) kmin = other;
            }
            if (r > 0 && lane == 0)
                g_knn[base + r - 1] = (int)(kmin & 0xffffffffu);
            if (key == kmin) {
                #pragma unroll
                for (int i = 0; i < 15; i++) { dl[i] = dl[i + 1]; il[i] = il[i + 1]; }
                dl[15] = 3.4e38f; il[15] = 0;
                key = packkey(dl[0], il[0]);
            }
        }
    }
}

// ---------------------------------------------------------------------------
// Kernel C: fused NN-merge + gather + MLPs. One warp per 2 points.
// All weight GEMV loads use transposed [c][o] layout: lane owns outputs
// o = 2*lane, 2*lane+1 (one float2 per c) -> coalesced, 2 lines/warp-load.
// ---------------------------------------------------------------------------
__global__ __launch_bounds__(256) void fused_kernel(
    const float* __restrict__ pcl,  const float* __restrict__ pcl_noise,
    const float* __restrict__ feature,
    const float* __restrict__ w2a,  const float* __restrict__ b2a,
    const float* __restrict__ g2a,  const float* __restrict__ bt2a,
    const float* __restrict__ b2b,
    const float* __restrict__ b1a,
    const float* __restrict__ g1a,  const float* __restrict__ bt1a,
    const float* __restrict__ b1b,
    float* __restrict__ out)
{
    const int wrp  = threadIdx.x >> 5;
    const int lane = threadIdx.x & 31;
    const int ptA  = blockIdx.x * 16 + wrp * 2;   // 2 points per warp
    const int ptB  = ptA + 1;
    const int bA = ptA >> 13, nA = ptA & (NN - 1);
    const int bB = ptB >> 13, nB = ptB & (NN - 1);

    __shared__ float s_df[8][2][3 * CC];
    __shared__ float s_h1[8][2][CC];

    const float invs = rsqrtf(1.0f + 1e-5f);
    const unsigned FULL = 0xffffffffu;

    // ---- merge partial NN keys (redundant across lanes; broadcast loads) ---
    unsigned long long kmA = 0xffffffffffffffffull, kmB = kmA;
    #pragma unroll
    for (int c = 0; c < NCHUNK; c++) {
        unsigned long long kA = g_nn_part[((size_t)bA * NCHUNK + c) * NN + nA];
        unsigned long long kB = g_nn_part[((size_t)bB * NCHUNK + c) * NN + nB];
        if (kA < kmA) kmA = kA;
        if (kB < kmB) kmB = kB;
    }
    const int ciA = (int)(kmA & 0xffffffffu);
    const int ciB = (int)(kmB & 0xffffffffu);

    const float qxA = pcl_noise[((size_t)bA * NN + nA) * 3 + 0];
    const float qyA = pcl_noise[((size_t)bA * NN + nA) * 3 + 1];
    const float qzA = pcl_noise[((size_t)bA * NN + nA) * 3 + 2];
    const float qxB = pcl_noise[((size_t)bB * NN + nB) * 3 + 0];
    const float qyB = pcl_noise[((size_t)bB * NN + nB) * 3 + 1];
    const float qzB = pcl_noise[((size_t)bB * NN + nB) * 3 + 2];
    const float cpxA = pcl[((size_t)bA * MM + ciA) * 3 + 0];
    const float cpyA = pcl[((size_t)bA * MM + ciA) * 3 + 1];
    const float cpzA = pcl[((size_t)bA * MM + ciA) * 3 + 2];
    const float cpxB = pcl[((size_t)bB * MM + ciB) * 3 + 0];
    const float cpyB = pcl[((size_t)bB * MM + ciB) * 3 + 1];
    const float cpzB = pcl[((size_t)bB * MM + ciB) * 3 + 2];

    // ---- lane k (<15) owns neighbor k of each point ------------------------
    int jkA = 0, jkB = 0;
    float ldxA = 0.f, ldyA = 0.f, ldzA = 0.f, eA = 0.f;
    float ldxB = 0.f, ldyB = 0.f, ldzB = 0.f, eB = 0.f;
    if (lane < KK) {
        jkA = g_knn[(bA * MM + ciA) * KK + lane];
        jkB = g_knn[(bB * MM + ciB) * KK + lane];
        float pxA = pcl[((size_t)bA * MM + jkA) * 3 + 0];
        float pyA = pcl[((size_t)bA * MM + jkA) * 3 + 1];
        float pzA = pcl[((size_t)bA * MM + jkA) * 3 + 2];
        float pxB = pcl[((size_t)bB * MM + jkB) * 3 + 0];
        float pyB = pcl[((size_t)bB * MM + jkB) * 3 + 1];
        float pzB = pcl[((size_t)bB * MM + jkB) * 3 + 2];
        ldxA = pxA - qxA; ldyA = pyA - qyA; ldzA = pzA - qzA;
        ldxB = pxB - qxB; ldyB = pyB - qyB; ldzB = pzB - qzB;
        eA = expf(-10.0f * sqrtf(ldxA * ldxA + ldyA * ldyA + ldzA * ldzA));
        eB = expf(-10.0f * sqrtf(ldxB * ldxB + ldyB * ldyB + ldzB * ldzB));
    }
    float SA = eA, SB = eB;
    #pragma unroll
    for (int o = 16; o; o >>= 1) {
        SA += __shfl_xor_sync(FULL, SA, o);
        SB += __shfl_xor_sync(FULL, SB, o);
    }
    const float lwA = eA / (SA + 1e-7f), ssumA = SA / (SA + 1e-7f);
    const float lwB = eB / (SB + 1e-7f), ssumB = SB / (SB + 1e-7f);

    // ---- layer 1 (6 -> 256, BN+ReLU), weighted-summed into hbar (regs) ----
    float a0[8], a1[8], a2[8], tA[8], tB[8], gsv[8], btv[8], hbA[8], hbB[8];
    #pragma unroll
    for (int i = 0; i < 8; i++) {
        const int c = lane + 32 * i;
        const float2 w01 = *(const float2*)(w2a + c * 6 + 0);
        const float2 w23 = *(const float2*)(w2a + c * 6 + 2);
        const float2 w45 = *(const float2*)(w2a + c * 6 + 4);
        a0[i] = w01.x; a1[i] = w01.y; a2[i] = w23.x;
        const float bb = b2a[c];
        tA[i] = w23.y * cpxA + w45.x * cpyA + w45.y * cpzA + bb;
        tB[i] = w23.y * cpxB + w45.x * cpyB + w45.y * cpzB + bb;
        gsv[i] = g2a[c] * invs;
        btv[i] = bt2a[c];
        hbA[i] = 0.f; hbB[i] = 0.f;
    }
    for (int k = 0; k < KK; k++) {
        const float kdxA = __shfl_sync(FULL, ldxA, k);
        const float kdyA = __shfl_sync(FULL, ldyA, k);
        const float kdzA = __shfl_sync(FULL, ldzA, k);
        const float kwA  = __shfl_sync(FULL, lwA,  k);
        const float kdxB = __shfl_sync(FULL, ldxB, k);
        const float kdyB = __shfl_sync(FULL, ldyB, k);
        const float kdzB = __shfl_sync(FULL, ldzB, k);
        const float kwB  = __shfl_sync(FULL, lwB,  k);
        #pragma unroll
        for (int i = 0; i < 8; i++) {
            float pA = a0[i] * kdxA + a1[i] * kdyA + a2[i] * kdzA + tA[i];
            float pB = a0[i] * kdxB + a1[i] * kdyB + a2[i] * kdzB + tB[i];
            hbA[i] += kwA * fmaxf(pA * gsv[i] + btv[i], 0.f);
            hbB[i] += kwB * fmaxf(pB * gsv[i] + btv[i], 0.f);
        }
    }

    // ---- layer 2: pf_o = sum_c wt2b[c][o]*hbar_c + b2b[o]*ssum -------------
    float pfA1 = 0.f, pfA2 = 0.f, pfB1 = 0.f, pfB2 = 0.f;
    #pragma unroll
    for (int i = 0; i < 8; i++) {
        #pragma unroll 4
        for (int s = 0; s < 32; s++) {
            const int c = 32 * i + s;
            const float hA = __shfl_sync(FULL, hbA[i], s);
            const float hB = __shfl_sync(FULL, hbB[i], s);
            const float2 wv = *(const float2*)(g_wt2b + c * CC + 2 * lane);
            pfA1 += wv.x * hA; pfA2 += wv.y * hA;
            pfB1 += wv.x * hB; pfB2 += wv.y * hB;
        }
    }
    const int o1 = 2 * lane, o2 = 2 * lane + 1;
    const float2 bb2 = *(const float2*)(b2b + o1);
    pfA1 += bb2.x * ssumA; pfA2 += bb2.y * ssumA;
    pfB1 += bb2.x * ssumB; pfB2 += bb2.y * ssumB;

    // ---- close_feat + co_feature (float2, coalesced) -----------------------
    const float2 cfA = *(const float2*)(feature + ((size_t)bA * MM + ciA) * CC + o1);
    const float2 cfB = *(const float2*)(feature + ((size_t)bB * MM + ciB) * CC + o1);
    float coA1 = 0.f, coA2 = 0.f, coB1 = 0.f, coB2 = 0.f;
    for (int k = 0; k < KK; k++) {
        const int   jA = __shfl_sync(FULL, jkA, k);
        const float wA = __shfl_sync(FULL, lwA, k);
        const int   jB = __shfl_sync(FULL, jkB, k);
        const float wB = __shfl_sync(FULL, lwB, k);
        const float2 fA = *(const float2*)(feature + ((size_t)bA * MM + jA) * CC + o1);
        const float2 fB = *(const float2*)(feature + ((size_t)bB * MM + jB) * CC + o1);
        coA1 += wA * fA.x; coA2 += wA * fA.y;
        coB1 += wB * fB.x; coB2 += wB * fB.y;
    }

    *(float2*)&s_df[wrp][0][o1]          = cfA;
    *(float2*)&s_df[wrp][1][o1]          = cfB;
    *(float2*)&s_df[wrp][0][CC + o1]     = make_float2(coA1, coA2);
    *(float2*)&s_df[wrp][1][CC + o1]     = make_float2(coB1, coB2);
    *(float2*)&s_df[wrp][0][2 * CC + o1] = make_float2(pfA1, pfA2);
    *(float2*)&s_df[wrp][1][2 * CC + o1] = make_float2(pfB1, pfB2);
    __syncwarp();

    // ---- final MLP layer 1: 192 -> 64, BN+ReLU -----------------------------
    float acA1 = 0.f, acA2 = 0.f, acB1 = 0.f, acB2 = 0.f;
    #pragma unroll 4
    for (int c = 0; c < 3 * CC; c++) {
        const float dA = s_df[wrp][0][c];
        const float dB = s_df[wrp][1][c];
        const float2 wv = *(const float2*)(g_wt1a + c * CC + o1);
        acA1 += wv.x * dA; acA2 += wv.y * dA;
        acB1 += wv.x * dB; acB2 += wv.y * dB;
    }
    const float2 bb1  = *(const float2*)(b1a + o1);
    const float2 gg1  = *(const float2*)(g1a + o1);
    const float2 bt1  = *(const float2*)(bt1a + o1);
    const float g1x = gg1.x * invs, g1y = gg1.y * invs;
    *(float2*)&s_h1[wrp][0][o1] = make_float2(
        fmaxf((acA1 + bb1.x) * g1x + bt1.x, 0.f),
        fmaxf((acA2 + bb1.y) * g1y + bt1.y, 0.f));
    *(float2*)&s_h1[wrp][1][o1] = make_float2(
        fmaxf((acB1 + bb1.x) * g1x + bt1.x, 0.f),
        fmaxf((acB2 + bb1.y) * g1y + bt1.y, 0.f));
    __syncwarp();

    // ---- final MLP layer 2: 64 -> 64 ---------------------------------------
    const float2 bbo = *(const float2*)(b1b + o1);
    float rA1 = bbo.x, rA2 = bbo.y, rB1 = bbo.x, rB2 = bbo.y;
    #pragma unroll 4
    for (int c = 0; c < CC; c++) {
        const float hA = s_h1[wrp][0][c];
        const float hB = s_h1[wrp][1][c];
        const float2 wv = *(const float2*)(g_wt1b + c * CC + o1);
        rA1 += wv.x * hA; rA2 += wv.y * hA;
        rB1 += wv.x * hB; rB2 += wv.y * hB;
    }
    *(float2*)(out + ((size_t)bA * NN + nA) * CC + o1) = make_float2(rA1, rA2);
    *(float2*)(out + ((size_t)bB * NN + nB) * CC + o1) = make_float2(rB1, rB2);
}

// ---------------------------------------------------------------------------
extern "C" void kernel_launch(void* const* d_in, const int* in_sizes, int n_in,
                              void* d_out, int out_size)
{
    (void)in_sizes; (void)n_in; (void)out_size;
    const float* pcl       = (const float*)d_in[0];
    const float* pcl_noise = (const float*)d_in[1];
    const float* feature   = (const float*)d_in[2];
    const float* w2a  = (const float*)d_in[3];
    const float* b2a  = (const float*)d_in[4];
    const float* g2a  = (const float*)d_in[5];
    const float* bt2a = (const float*)d_in[6];
    const float* w2b  = (const float*)d_in[7];
    const float* b2b  = (const float*)d_in[8];
    const float* w1a  = (const float*)d_in[9];
    const float* b1a  = (const float*)d_in[10];
    const float* g1a  = (const float*)d_in[11];
    const float* bt1a = (const float*)d_in[12];
    const float* w1b  = (const float*)d_in[13];
    const float* b1b  = (const float*)d_in[14];
    float* out = (float*)d_out;

    transpose_kernel<<<32, 256>>>(w2b, w1a, w1b);
    nn_part_kernel<<<dim3(NN / 128, NCHUNK, BB), 128>>>(pcl, pcl_noise);
    knn_kernel<<<dim3(MM / 16, BB), 128>>>(pcl);
    fused_kernel<<<(BB * NN) / 16, 256>>>(
        pcl, pcl_noise, feature,
        w2a, b2a, g2a, bt2a, b2b,
        b1a, g1a, bt1a, b1b, out);
}

// round 4
// speedup vs baseline: 4.2497x; 1.5275x over previous
#include <cuda_runtime.h>
#include <math.h>

#define BB  2
#define NN  8192
#define MM  4096
#define CC  64
#define KK  15      // K-1 neighbors actually used
#define HH  256
#define NCHUNK 8
#define CHM (MM / NCHUNK)   // 512

// Scratch (allocation-free rule: __device__ globals)
__device__ unsigned long long g_nn_part[BB * NCHUNK * NN];
__device__ int   g_knn[BB * MM * KK];
__device__ float g_wt2b[HH * CC];        // [c][o]
__device__ float g_wt1a[3 * CC * CC];    // [c][o]
__device__ float g_wt1b[CC * CC];        // [c][o]

static __device__ __forceinline__ unsigned long long packkey(float d, int idx) {
    return ((unsigned long long)__float_as_uint(d) << 32) | (unsigned)idx;
}

// ---------------------------------------------------------------------------
// Kernel P: transpose weights into [c][o] layout for coalesced GEMV loads.
// ---------------------------------------------------------------------------
__global__ __launch_bounds__(256) void transpose_kernel(
    const float* __restrict__ w2b, const float* __restrict__ w1a,
    const float* __restrict__ w1b)
{
    const int t = blockIdx.x * 256 + threadIdx.x;
    const int stride = gridDim.x * 256;
    for (int idx = t; idx < HH * CC; idx += stride) {
        int c = idx / CC, o = idx - c * CC;
        g_wt2b[idx] = w2b[o * HH + c];
    }
    for (int idx = t; idx < 3 * CC * CC; idx += stride) {
        int c = idx / CC, o = idx - c * CC;
        g_wt1a[idx] = w1a[o * (3 * CC) + c];
    }
    for (int idx = t; idx < CC * CC; idx += stride) {
        int c = idx / CC, o = idx - c * CC;
        g_wt1b[idx] = w1b[o * CC + c];
    }
}

// ---------------------------------------------------------------------------
// Kernel A: partial argmin over a 512-candidate chunk of pcl, per noisy pt.
// ---------------------------------------------------------------------------
__global__ __launch_bounds__(128) void nn_part_kernel(
    const float* __restrict__ pcl, const float* __restrict__ pcl_noise)
{
    const int b = blockIdx.z;
    const int chunk = blockIdx.y;
    const int n = blockIdx.x * 128 + threadIdx.x;
    const float* pb = pcl + (size_t)b * MM * 3 + (size_t)chunk * CHM * 3;

    const float qx = pcl_noise[((size_t)b * NN + n) * 3 + 0];
    const float qy = pcl_noise[((size_t)b * NN + n) * 3 + 1];
    const float qz = pcl_noise[((size_t)b * NN + n) * 3 + 2];

    __shared__ float sp[3 * CHM];
    for (int i = threadIdx.x; i < (3 * CHM) / 4; i += 128)
        ((float4*)sp)[i] = ((const float4*)pb)[i];
    __syncthreads();

    float best = 3.4e38f;
    int   bi   = 0;

    const float4* sp4 = (const float4*)sp;
    #pragma unroll 4
    for (int j = 0; j < CHM; j += 4) {
        const int f4 = (j * 3) >> 2;
        float4 a = sp4[f4], c1 = sp4[f4 + 1], c2 = sp4[f4 + 2];
        float dx, dy, dz;
        dx = a.x - qx;  dy = a.y - qy;  dz = a.z - qz;
        float d0 = dx * dx + dy * dy + dz * dz;
        dx = a.w - qx;  dy = c1.x - qy; dz = c1.y - qz;
        float d1 = dx * dx + dy * dy + dz * dz;
        dx = c1.z - qx; dy = c1.w - qy; dz = c2.x - qz;
        float d2 = dx * dx + dy * dy + dz * dz;
        dx = c2.y - qx; dy = c2.z - qy; dz = c2.w - qz;
        float d3 = dx * dx + dy * dy + dz * dz;

        if (d0 < best) { best = d0; bi = j;     }
        if (d1 < best) { best = d1; bi = j + 1; }
        if (d2 < best) { best = d2; bi = j + 2; }
        if (d3 < best) { best = d3; bi = j + 3; }
    }
    g_nn_part[((size_t)b * NCHUNK + chunk) * NN + n] =
        packkey(best, chunk * CHM + bi);
}

// ---------------------------------------------------------------------------
// Kernel B: self-KNN of pcl. Warp-per-query with a warp-DISTRIBUTED sorted
// top-16: lanes 0..15 hold the running list (packed u64 keys, ascending).
// Per scan iteration: 32 candidate dists, ballot vs cached kmax; only
// passing candidates (expected ~150/query total) take the O(1) cooperative
// insert (position ballot + single shfl_up shift). Key order == top_k tie
// semantics (lower index wins on equal distance).
// ---------------------------------------------------------------------------
__global__ __launch_bounds__(128) void knn_kernel(const float* __restrict__ pcl)
{
    const int b = blockIdx.y;
    const int wrp  = threadIdx.x >> 5;
    const int lane = threadIdx.x & 31;
    const float* pb = pcl + (size_t)b * MM * 3;
    const unsigned FULL = 0xffffffffu;

    __shared__ float sx[MM], sy[MM], sz[MM];
    for (int i = threadIdx.x; i < 3 * MM; i += 128) {
        float v = pb[i];
        int m = i / 3, c = i - 3 * m;
        if (c == 0) sx[m] = v; else if (c == 1) sy[m] = v; else sz[m] = v;
    }
    __syncthreads();

    for (int q = 0; q < 4; q++) {
        const int m = blockIdx.x * 16 + wrp * 4 + q;
        const float qx = sx[m], qy = sy[m], qz = sz[m];

        unsigned long long key = 0xffffffffffffffffull;   // lanes 0..15 = list
        unsigned long long kmax = 0xffffffffffffffffull;  // = key[15]

        for (int t = 0; t < MM / 32; t++) {
            const int j = lane + 32 * t;
            const float dx = sx[j] - qx, dy = sy[j] - qy, dz = sz[j] - qz;
            const float dc = dx * dx + dy * dy + dz * dz;
            const unsigned long long kc_mine = packkey(dc, j);

            unsigned pending = __ballot_sync(FULL, kc_mine < kmax);
            while (pending) {
                const int src = __ffs(pending) - 1;
                pending &= pending - 1;
                const unsigned long long kc = __shfl_sync(FULL, kc_mine, src);
                if (kc < kmax) {
                    // insertion position among lanes 0..15
                    const unsigned bal =
                        __ballot_sync(FULL, key > kc) & 0xFFFFu;
                    const int p = __ffs(bal) - 1;   // 0..15 (lane15 qualifies)
                    const unsigned long long up = __shfl_up_sync(FULL, key, 1);
                    if (lane == p)      key = kc;
                    else if (lane > p)  key = up;
                    kmax = __shfl_sync(FULL, key, 15);
                } else {
                    __syncwarp(FULL);
                }
            }
        }

        // rank 0 is the self point (d = 0); emit ranks 1..15
        const int base = (b * MM + m) * KK;
        if (lane >= 1 && lane <= KK)
            g_knn[base + lane - 1] = (int)(key & 0xffffffffu);
    }
}

// ---------------------------------------------------------------------------
// Kernel C: fused NN-merge + gather + MLPs. One warp per 2 points.
// All weight GEMV loads use transposed [c][o] layout: lane owns outputs
// o = 2*lane, 2*lane+1 (one float2 per c) -> coalesced, 2 lines/warp-load.
// ---------------------------------------------------------------------------
__global__ __launch_bounds__(256) void fused_kernel(
    const float* __restrict__ pcl,  const float* __restrict__ pcl_noise,
    const float* __restrict__ feature,
    const float* __restrict__ w2a,  const float* __restrict__ b2a,
    const float* __restrict__ g2a,  const float* __restrict__ bt2a,
    const float* __restrict__ b2b,
    const float* __restrict__ b1a,
    const float* __restrict__ g1a,  const float* __restrict__ bt1a,
    const float* __restrict__ b1b,
    float* __restrict__ out)
{
    const int wrp  = threadIdx.x >> 5;
    const int lane = threadIdx.x & 31;
    const int ptA  = blockIdx.x * 16 + wrp * 2;   // 2 points per warp
    const int ptB  = ptA + 1;
    const int bA = ptA >> 13, nA = ptA & (NN - 1);
    const int bB = ptB >> 13, nB = ptB & (NN - 1);

    __shared__ float s_df[8][2][3 * CC];
    __shared__ float s_h1[8][2][CC];

    const float invs = rsqrtf(1.0f + 1e-5f);
    const unsigned FULL = 0xffffffffu;

    // ---- merge partial NN keys (redundant across lanes; broadcast loads) ---
    unsigned long long kmA = 0xffffffffffffffffull, kmB = kmA;
    #pragma unroll
    for (int c = 0; c < NCHUNK; c++) {
        unsigned long long kA = g_nn_part[((size_t)bA * NCHUNK + c) * NN + nA];
        unsigned long long kB = g_nn_part[((size_t)bB * NCHUNK + c) * NN + nB];
        if (kA < kmA) kmA = kA;
        if (kB < kmB) kmB = kB;
    }
    const int ciA = (int)(kmA & 0xffffffffu);
    const int ciB = (int)(kmB & 0xffffffffu);

    const float qxA = pcl_noise[((size_t)bA * NN + nA) * 3 + 0];
    const float qyA = pcl_noise[((size_t)bA * NN + nA) * 3 + 1];
    const float qzA = pcl_noise[((size_t)bA * NN + nA) * 3 + 2];
    const float qxB = pcl_noise[((size_t)bB * NN + nB) * 3 + 0];
    const float qyB = pcl_noise[((size_t)bB * NN + nB) * 3 + 1];
    const float qzB = pcl_noise[((size_t)bB * NN + nB) * 3 + 2];
    const float cpxA = pcl[((size_t)bA * MM + ciA) * 3 + 0];
    const float cpyA = pcl[((size_t)bA * MM + ciA) * 3 + 1];
    const float cpzA = pcl[((size_t)bA * MM + ciA) * 3 + 2];
    const float cpxB = pcl[((size_t)bB * MM + ciB) * 3 + 0];
    const float cpyB = pcl[((size_t)bB * MM + ciB) * 3 + 1];
    const float cpzB = pcl[((size_t)bB * MM + ciB) * 3 + 2];

    // ---- lane k (<15) owns neighbor k of each point ------------------------
    int jkA = 0, jkB = 0;
    float ldxA = 0.f, ldyA = 0.f, ldzA = 0.f, eA = 0.f;
    float ldxB = 0.f, ldyB = 0.f, ldzB = 0.f, eB = 0.f;
    if (lane < KK) {
        jkA = g_knn[(bA * MM + ciA) * KK + lane];
        jkB = g_knn[(bB * MM + ciB) * KK + lane];
        float pxA = pcl[((size_t)bA * MM + jkA) * 3 + 0];
        float pyA = pcl[((size_t)bA * MM + jkA) * 3 + 1];
        float pzA = pcl[((size_t)bA * MM + jkA) * 3 + 2];
        float pxB = pcl[((size_t)bB * MM + jkB) * 3 + 0];
        float pyB = pcl[((size_t)bB * MM + jkB) * 3 + 1];
        float pzB = pcl[((size_t)bB * MM + jkB) * 3 + 2];
        ldxA = pxA - qxA; ldyA = pyA - qyA; ldzA = pzA - qzA;
        ldxB = pxB - qxB; ldyB = pyB - qyB; ldzB = pzB - qzB;
        eA = expf(-10.0f * sqrtf(ldxA * ldxA + ldyA * ldyA + ldzA * ldzA));
        eB = expf(-10.0f * sqrtf(ldxB * ldxB + ldyB * ldyB + ldzB * ldzB));
    }
    float SA = eA, SB = eB;
    #pragma unroll
    for (int o = 16; o; o >>= 1) {
        SA += __shfl_xor_sync(FULL, SA, o);
        SB += __shfl_xor_sync(FULL, SB, o);
    }
    const float lwA = eA / (SA + 1e-7f), ssumA = SA / (SA + 1e-7f);
    const float lwB = eB / (SB + 1e-7f), ssumB = SB / (SB + 1e-7f);

    // ---- layer 1 (6 -> 256, BN+ReLU), weighted-summed into hbar (regs) ----
    float a0[8], a1[8], a2[8], tA[8], tB[8], gsv[8], btv[8], hbA[8], hbB[8];
    #pragma unroll
    for (int i = 0; i < 8; i++) {
        const int c = lane + 32 * i;
        const float2 w01 = *(const float2*)(w2a + c * 6 + 0);
        const float2 w23 = *(const float2*)(w2a + c * 6 + 2);
        const float2 w45 = *(const float2*)(w2a + c * 6 + 4);
        a0[i] = w01.x; a1[i] = w01.y; a2[i] = w23.x;
        const float bb = b2a[c];
        tA[i] = w23.y * cpxA + w45.x * cpyA + w45.y * cpzA + bb;
        tB[i] = w23.y * cpxB + w45.x * cpyB + w45.y * cpzB + bb;
        gsv[i] = g2a[c] * invs;
        btv[i] = bt2a[c];
        hbA[i] = 0.f; hbB[i] = 0.f;
    }
    for (int k = 0; k < KK; k++) {
        const float kdxA = __shfl_sync(FULL, ldxA, k);
        const float kdyA = __shfl_sync(FULL, ldyA, k);
        const float kdzA = __shfl_sync(FULL, ldzA, k);
        const float kwA  = __shfl_sync(FULL, lwA,  k);
        const float kdxB = __shfl_sync(FULL, ldxB, k);
        const float kdyB = __shfl_sync(FULL, ldyB, k);
        const float kdzB = __shfl_sync(FULL, ldzB, k);
        const float kwB  = __shfl_sync(FULL, lwB,  k);
        #pragma unroll
        for (int i = 0; i < 8; i++) {
            float pA = a0[i] * kdxA + a1[i] * kdyA + a2[i] * kdzA + tA[i];
            float pB = a0[i] * kdxB + a1[i] * kdyB + a2[i] * kdzB + tB[i];
            hbA[i] += kwA * fmaxf(pA * gsv[i] + btv[i], 0.f);
            hbB[i] += kwB * fmaxf(pB * gsv[i] + btv[i], 0.f);
        }
    }

    // ---- layer 2: pf_o = sum_c wt2b[c][o]*hbar_c + b2b[o]*ssum -------------
    float pfA1 = 0.f, pfA2 = 0.f, pfB1 = 0.f, pfB2 = 0.f;
    #pragma unroll
    for (int i = 0; i < 8; i++) {
        #pragma unroll 4
        for (int s = 0; s < 32; s++) {
            const int c = 32 * i + s;
            const float hA = __shfl_sync(FULL, hbA[i], s);
            const float hB = __shfl_sync(FULL, hbB[i], s);
            const float2 wv = *(const float2*)(g_wt2b + c * CC + 2 * lane);
            pfA1 += wv.x * hA; pfA2 += wv.y * hA;
            pfB1 += wv.x * hB; pfB2 += wv.y * hB;
        }
    }
    const int o1 = 2 * lane, o2 = 2 * lane + 1;
    const float2 bb2 = *(const float2*)(b2b + o1);
    pfA1 += bb2.x * ssumA; pfA2 += bb2.y * ssumA;
    pfB1 += bb2.x * ssumB; pfB2 += bb2.y * ssumB;

    // ---- close_feat + co_feature (float2, coalesced) -----------------------
    const float2 cfA = *(const float2*)(feature + ((size_t)bA * MM + ciA) * CC + o1);
    const float2 cfB = *(const float2*)(feature + ((size_t)bB * MM + ciB) * CC + o1);
    float coA1 = 0.f, coA2 = 0.f, coB1 = 0.f, coB2 = 0.f;
    for (int k = 0; k < KK; k++) {
        const int   jA = __shfl_sync(FULL, jkA, k);
        const float wA = __shfl_sync(FULL, lwA, k);
        const int   jB = __shfl_sync(FULL, jkB, k);
        const float wB = __shfl_sync(FULL, lwB, k);
        const float2 fA = *(const float2*)(feature + ((size_t)bA * MM + jA) * CC + o1);
        const float2 fB = *(const float2*)(feature + ((size_t)bB * MM + jB) * CC + o1);
        coA1 += wA * fA.x; coA2 += wA * fA.y;
        coB1 += wB * fB.x; coB2 += wB * fB.y;
    }

    *(float2*)&s_df[wrp][0][o1]          = cfA;
    *(float2*)&s_df[wrp][1][o1]          = cfB;
    *(float2*)&s_df[wrp][0][CC + o1]     = make_float2(coA1, coA2);
    *(float2*)&s_df[wrp][1][CC + o1]     = make_float2(coB1, coB2);
    *(float2*)&s_df[wrp][0][2 * CC + o1] = make_float2(pfA1, pfA2);
    *(float2*)&s_df[wrp][1][2 * CC + o1] = make_float2(pfB1, pfB2);
    __syncwarp();

    // ---- final MLP layer 1: 192 -> 64, BN+ReLU -----------------------------
    float acA1 = 0.f, acA2 = 0.f, acB1 = 0.f, acB2 = 0.f;
    #pragma unroll 4
    for (int c = 0; c < 3 * CC; c++) {
        const float dA = s_df[wrp][0][c];
        const float dB = s_df[wrp][1][c];
        const float2 wv = *(const float2*)(g_wt1a + c * CC + o1);
        acA1 += wv.x * dA; acA2 += wv.y * dA;
        acB1 += wv.x * dB; acB2 += wv.y * dB;
    }
    const float2 bb1  = *(const float2*)(b1a + o1);
    const float2 gg1  = *(const float2*)(g1a + o1);
    const float2 bt1  = *(const float2*)(bt1a + o1);
    const float g1x = gg1.x * invs, g1y = gg1.y * invs;
    *(float2*)&s_h1[wrp][0][o1] = make_float2(
        fmaxf((acA1 + bb1.x) * g1x + bt1.x, 0.f),
        fmaxf((acA2 + bb1.y) * g1y + bt1.y, 0.f));
    *(float2*)&s_h1[wrp][1][o1] = make_float2(
        fmaxf((acB1 + bb1.x) * g1x + bt1.x, 0.f),
        fmaxf((acB2 + bb1.y) * g1y + bt1.y, 0.f));
    __syncwarp();

    // ---- final MLP layer 2: 64 -> 64 ---------------------------------------
    const float2 bbo = *(const float2*)(b1b + o1);
    float rA1 = bbo.x, rA2 = bbo.y, rB1 = bbo.x, rB2 = bbo.y;
    #pragma unroll 4
    for (int c = 0; c < CC; c++) {
        const float hA = s_h1[wrp][0][c];
        const float hB = s_h1[wrp][1][c];
        const float2 wv = *(const float2*)(g_wt1b + c * CC + o1);
        rA1 += wv.x * hA; rA2 += wv.y * hA;
        rB1 += wv.x * hB; rB2 += wv.y * hB;
    }
    *(float2*)(out + ((size_t)bA * NN + nA) * CC + o1) = make_float2(rA1, rA2);
    *(float2*)(out + ((size_t)bB * NN + nB) * CC + o1) = make_float2(rB1, rB2);
}

// ---------------------------------------------------------------------------
extern "C" void kernel_launch(void* const* d_in, const int* in_sizes, int n_in,
                              void* d_out, int out_size)
{
    (void)in_sizes; (void)n_in; (void)out_size;
    const float* pcl       = (const float*)d_in[0];
    const float* pcl_noise = (const float*)d_in[1];
    const float* feature   = (const float*)d_in[2];
    const float* w2a  = (const float*)d_in[3];
    const float* b2a  = (const float*)d_in[4];
    const float* g2a  = (const float*)d_in[5];
    const float* bt2a = (const float*)d_in[6];
    const float* w2b  = (const float*)d_in[7];
    const float* b2b  = (const float*)d_in[8];
    const float* w1a  = (const float*)d_in[9];
    const float* b1a  = (const float*)d_in[10];
    const float* g1a  = (const float*)d_in[11];
    const float* bt1a = (const float*)d_in[12];
    const float* w1b  = (const float*)d_in[13];
    const float* b1b  = (const float*)d_in[14];
    float* out = (float*)d_out;

    transpose_kernel<<<32, 256>>>(w2b, w1a, w1b);
    nn_part_kernel<<<dim3(NN / 128, NCHUNK, BB), 128>>>(pcl, pcl_noise);
    knn_kernel<<<dim3(MM / 16, BB), 128>>>(pcl);
    fused_kernel<<<(BB * NN) / 16, 256>>>(
        pcl, pcl_noise, feature,
        w2a, b2a, g2a, bt2a, b2b,
        b1a, g1a, bt1a, b1b, out);
}

// round 5
// speedup vs baseline: 5.3167x; 1.2511x over previous
#include <cuda_runtime.h>
#include <math.h>

#define BB  2
#define NN  8192
#define MM  4096
#define CC  64
#define KK  15      // K-1 neighbors actually used
#define HH  256
#define NCHUNK 8
#define CHM (MM / NCHUNK)   // 512

// Scratch (allocation-free rule: __device__ globals)
__device__ unsigned long long g_nn_part[BB * NCHUNK * NN];
__device__ int   g_knn[BB * MM * KK];
// prepped weights
__device__ float g_l1A[HH * 4];            // [c][{A0,A1,A2,B}]  (BN-folded)
__device__ float g_l1T[HH * 4];            // [c][{A3,A4,A5,0}]  (BN-folded)
__device__ float g_w2bd[HH * 2 * CC];      // [c][{w(o),w(o)} x 64]  dup pairs
__device__ float g_w1ad[3 * CC * 2 * CC];  // [c][dup pairs]
__device__ float g_w1bd[CC * 2 * CC];      // [c][dup pairs]
__device__ float g_f1s[CC];                // g1a*invs
__device__ float g_f1b[CC];                // b1a*g' + bt1a

#define FMA2(acc, a, b) \
    asm("fma.rn.f32x2 %0, %1, %2, %0;" : "+l"(acc) : "l"(a), "l"(b))
#define UNPK2(lo, hi, v) \
    asm("mov.b64 {%0, %1}, %2;" : "=f"(lo), "=f"(hi) : "l"(v))

static __device__ __forceinline__ unsigned long long packkey(float d, int idx) {
    return ((unsigned long long)__float_as_uint(d) << 32) | (unsigned)idx;
}

// ---------------------------------------------------------------------------
// Kernel P: fold BN + transpose + duplicate-pair weight prep.
// ---------------------------------------------------------------------------
__global__ __launch_bounds__(256) void prep_kernel(
    const float* __restrict__ w2a, const float* __restrict__ b2a,
    const float* __restrict__ g2a, const float* __restrict__ bt2a,
    const float* __restrict__ w2b,
    const float* __restrict__ w1a, const float* __restrict__ b1a,
    const float* __restrict__ g1a, const float* __restrict__ bt1a,
    const float* __restrict__ w1b)
{
    const float invs = rsqrtf(1.0f + 1e-5f);
    const int t = blockIdx.x * 256 + threadIdx.x;
    const int stride = gridDim.x * 256;

    for (int c = t; c < HH; c += stride) {
        const float gp = g2a[c] * invs;
        g_l1A[c * 4 + 0] = w2a[c * 6 + 0] * gp;
        g_l1A[c * 4 + 1] = w2a[c * 6 + 1] * gp;
        g_l1A[c * 4 + 2] = w2a[c * 6 + 2] * gp;
        g_l1A[c * 4 + 3] = b2a[c] * gp + bt2a[c];
        g_l1T[c * 4 + 0] = w2a[c * 6 + 3] * gp;
        g_l1T[c * 4 + 1] = w2a[c * 6 + 4] * gp;
        g_l1T[c * 4 + 2] = w2a[c * 6 + 5] * gp;
        g_l1T[c * 4 + 3] = 0.f;
    }
    for (int idx = t; idx < HH * CC; idx += stride) {
        int c = idx / CC, o = idx - c * CC;
        float v = w2b[o * HH + c];
        g_w2bd[c * 2 * CC + 2 * o + 0] = v;
        g_w2bd[c * 2 * CC + 2 * o + 1] = v;
    }
    for (int idx = t; idx < 3 * CC * CC; idx += stride) {
        int c = idx / CC, o = idx - c * CC;
        float v = w1a[o * (3 * CC) + c];
        g_w1ad[c * 2 * CC + 2 * o + 0] = v;
        g_w1ad[c * 2 * CC + 2 * o + 1] = v;
    }
    for (int idx = t; idx < CC * CC; idx += stride) {
        int c = idx / CC, o = idx - c * CC;
        float v = w1b[o * CC + c];
        g_w1bd[c * 2 * CC + 2 * o + 0] = v;
        g_w1bd[c * 2 * CC + 2 * o + 1] = v;
    }
    for (int o = t; o < CC; o += stride) {
        const float s = g1a[o] * invs;
        g_f1s[o] = s;
        g_f1b[o] = b1a[o] * s + bt1a[o];
    }
}

// ---------------------------------------------------------------------------
// Kernel A: partial argmin over a 512-candidate chunk of pcl, per noisy pt.
// ---------------------------------------------------------------------------
__global__ __launch_bounds__(128) void nn_part_kernel(
    const float* __restrict__ pcl, const float* __restrict__ pcl_noise)
{
    const int b = blockIdx.z;
    const int chunk = blockIdx.y;
    const int n = blockIdx.x * 128 + threadIdx.x;
    const float* pb = pcl + (size_t)b * MM * 3 + (size_t)chunk * CHM * 3;

    const float qx = pcl_noise[((size_t)b * NN + n) * 3 + 0];
    const float qy = pcl_noise[((size_t)b * NN + n) * 3 + 1];
    const float qz = pcl_noise[((size_t)b * NN + n) * 3 + 2];

    __shared__ float sp[3 * CHM];
    for (int i = threadIdx.x; i < (3 * CHM) / 4; i += 128)
        ((float4*)sp)[i] = ((const float4*)pb)[i];
    __syncthreads();

    float best = 3.4e38f;
    int   bi   = 0;

    const float4* sp4 = (const float4*)sp;
    #pragma unroll 4
    for (int j = 0; j < CHM; j += 4) {
        const int f4 = (j * 3) >> 2;
        float4 a = sp4[f4], c1 = sp4[f4 + 1], c2 = sp4[f4 + 2];
        float dx, dy, dz;
        dx = a.x - qx;  dy = a.y - qy;  dz = a.z - qz;
        float d0 = dx * dx + dy * dy + dz * dz;
        dx = a.w - qx;  dy = c1.x - qy; dz = c1.y - qz;
        float d1 = dx * dx + dy * dy + dz * dz;
        dx = c1.z - qx; dy = c1.w - qy; dz = c2.x - qz;
        float d2 = dx * dx + dy * dy + dz * dz;
        dx = c2.y - qx; dy = c2.z - qy; dz = c2.w - qz;
        float d3 = dx * dx + dy * dy + dz * dz;

        if (d0 < best) { best = d0; bi = j;     }
        if (d1 < best) { best = d1; bi = j + 1; }
        if (d2 < best) { best = d2; bi = j + 2; }
        if (d3 < best) { best = d3; bi = j + 3; }
    }
    g_nn_part[((size_t)b * NCHUNK + chunk) * NN + n] =
        packkey(best, chunk * CHM + bi);
}

// ---------------------------------------------------------------------------
// Kernel B: self-KNN, warp per 4 queries, 4-way interleaved scan.
// Distributed sorted top-16 in lanes 0..15 (u64 keys). Float prefilter
// (dc <= kmax_dist); exact u64 key compare inside the rare insert path.
// ---------------------------------------------------------------------------
__global__ __launch_bounds__(128) void knn_kernel(const float* __restrict__ pcl)
{
    const int b = blockIdx.y;
    const int wrp  = threadIdx.x >> 5;
    const int lane = threadIdx.x & 31;
    const float* pb = pcl + (size_t)b * MM * 3;
    const unsigned FULL = 0xffffffffu;

    __shared__ float sx[MM], sy[MM], sz[MM];
    for (int i = threadIdx.x; i < 3 * MM; i += 128) {
        float v = pb[i];
        int m = i / 3, c = i - 3 * m;
        if (c == 0) sx[m] = v; else if (c == 1) sy[m] = v; else sz[m] = v;
    }
    __syncthreads();

    const int m0 = blockIdx.x * 16 + wrp * 4;
    float qx[4], qy[4], qz[4];
    #pragma unroll
    for (int q = 0; q < 4; q++) {
        qx[q] = sx[m0 + q]; qy[q] = sy[m0 + q]; qz[q] = sz[m0 + q];
    }

    unsigned long long key[4], kmk[4];
    float kmd[4];
    #pragma unroll
    for (int q = 0; q < 4; q++) {
        key[q] = 0xffffffffffffffffull;
        kmk[q] = 0xffffffffffffffffull;
        kmd[q] = 3.4e38f;
    }

    for (int t = 0; t < MM / 32; t++) {
        const int j = lane + 32 * t;
        const float x = sx[j], y = sy[j], z = sz[j];
        float d[4];
        #pragma unroll
        for (int q = 0; q < 4; q++) {
            const float dx = x - qx[q], dy = y - qy[q], dz = z - qz[q];
            d[q] = dx * dx + dy * dy + dz * dz;
        }
        #pragma unroll
        for (int q = 0; q < 4; q++) {
            unsigned pend = __ballot_sync(FULL, d[q] <= kmd[q]);
            while (pend) {
                const int src = __ffs(pend) - 1;
                pend &= pend - 1;
                const float dc = __shfl_sync(FULL, d[q], src);
                const unsigned long long kc = packkey(dc, src + 32 * t);
                if (kc < kmk[q]) {
                    const unsigned bal =
                        __ballot_sync(FULL, key[q] > kc) & 0xFFFFu;
                    const int p = __ffs(bal) - 1;
                    const unsigned long long up =
                        __shfl_up_sync(FULL, key[q], 1);
                    if (lane == p)      key[q] = kc;
                    else if (lane > p)  key[q] = up;
                    kmk[q] = __shfl_sync(FULL, key[q], 15);
                    kmd[q] = __uint_as_float((unsigned)(kmk[q] >> 32));
                }
            }
        }
    }

    #pragma unroll
    for (int q = 0; q < 4; q++) {
        const int base = (b * MM + m0 + q) * KK;
        if (lane >= 1 && lane <= KK)
            g_knn[base + lane - 1] = (int)(key[q] & 0xffffffffu);
    }
}

// ---------------------------------------------------------------------------
// Kernel C: fused NN-merge + gather + MLPs. One warp per 4 points.
// Activations staged channel-major [c][4pts] in smem; weights pre-duplicated
// {w,w} pairs -> each GEMV channel = 1 LDS.128 + 1 LDG.128 + 4 FFMA2 (16 MACs).
// ---------------------------------------------------------------------------
struct __align__(16) WarpSm {
    float kd[4][16][4];   // [p][k][dx,dy,dz,lw]
    float jw[4][16][2];   // [p][k][jk(bits), lw]
    float hb[HH][4];      // hbar, channel-major
    float df[3 * CC][4];  // df, channel-major
    float h1[CC][4];
};

__global__ __launch_bounds__(128) void fused_kernel(
    const float* __restrict__ pcl,  const float* __restrict__ pcl_noise,
    const float* __restrict__ feature,
    const float* __restrict__ b2b,  const float* __restrict__ b1b,
    float* __restrict__ out)
{
    const int wrp  = threadIdx.x >> 5;
    const int lane = threadIdx.x & 31;
    const int pt0  = (blockIdx.x * 4 + wrp) * 4;   // 4 consecutive points
    const int b    = pt0 >> 13;
    const int n0   = pt0 & (NN - 1);
    const unsigned FULL = 0xffffffffu;

    __shared__ WarpSm sm[4];
    WarpSm& S = sm[wrp];

    // ---- distributed NN-merge: lane = p*8 + chunk --------------------------
    int ci[4];
    {
        const int p = lane >> 3, c = lane & 7;
        unsigned long long k =
            g_nn_part[((size_t)b * NCHUNK + c) * NN + (n0 + p)];
        unsigned long long o;
        o = __shfl_xor_sync(FULL, k, 4); if (o < k) k = o;
        o = __shfl_xor_sync(FULL, k, 2); if (o < k) k = o;
        o = __shfl_xor_sync(FULL, k, 1); if (o < k) k = o;
        #pragma unroll
        for (int p2 = 0; p2 < 4; p2++)
            ci[p2] = (int)(__shfl_sync(FULL, k, p2 * 8) & 0xffffffffu);
    }

    // ---- query coords (3x LDG.128 broadcast) + close points ----------------
    float qx[4], qy[4], qz[4], cpx[4], cpy[4], cpz[4];
    {
        const float4* q4 =
            (const float4*)(pcl_noise + ((size_t)b * NN + n0) * 3);
        const float4 Q0 = q4[0], Q1 = q4[1], Q2 = q4[2];
        qx[0] = Q0.x; qy[0] = Q0.y; qz[0] = Q0.z;
        qx[1] = Q0.w; qy[1] = Q1.x; qz[1] = Q1.y;
        qx[2] = Q1.z; qy[2] = Q1.w; qz[2] = Q2.x;
        qx[3] = Q2.y; qy[3] = Q2.z; qz[3] = Q2.w;
        #pragma unroll
        for (int p = 0; p < 4; p++) {
            const float* cp = pcl + ((size_t)b * MM + ci[p]) * 3;
            cpx[p] = cp[0]; cpy[p] = cp[1]; cpz[p] = cp[2];
        }
    }

    // ---- neighbors: lane k owns neighbor k of each point -------------------
    float ssum[4];
    #pragma unroll
    for (int p = 0; p < 4; p++) {
        int jk = 0; float dx = 0.f, dy = 0.f, dz = 0.f, e = 0.f;
        if (lane < KK) {
            jk = g_knn[(b * MM + ci[p]) * KK + lane];
            const float* pp = pcl + ((size_t)b * MM + jk) * 3;
            dx = pp[0] - qx[p]; dy = pp[1] - qy[p]; dz = pp[2] - qz[p];
            e = expf(-10.0f * sqrtf(dx * dx + dy * dy + dz * dz));
        }
        float Sv = e;
        #pragma unroll
        for (int o = 16; o; o >>= 1) Sv += __shfl_xor_sync(FULL, Sv, o);
        const float lw = e / (Sv + 1e-7f);
        ssum[p] = Sv / (Sv + 1e-7f);
        if (lane < KK) {
            *(float4*)&S.kd[p][lane][0] = make_float4(dx, dy, dz, lw);
            *(float2*)&S.jw[p][lane][0] =
                make_float2(__int_as_float(jk), lw);
        }
    }
    __syncwarp();

    // ---- layer 1 (6 -> 256, BN folded), 2 passes of 2 points ---------------
    #pragma unroll
    for (int s = 0; s < 2; s++) {
        const int p0 = 2 * s, p1 = 2 * s + 1;
        float A0[8], A1[8], A2[8], t0[8], t1[8], h0[8], h1v[8];
        #pragma unroll
        for (int i = 0; i < 8; i++) {
            const int c = lane + 32 * i;
            const float4 wA = *(const float4*)&g_l1A[c * 4];
            const float4 wT = *(const float4*)&g_l1T[c * 4];
            A0[i] = wA.x; A1[i] = wA.y; A2[i] = wA.z;
            t0[i] = fmaf(wT.x, cpx[p0], fmaf(wT.y, cpy[p0],
                     fmaf(wT.z, cpz[p0], wA.w)));
            t1[i] = fmaf(wT.x, cpx[p1], fmaf(wT.y, cpy[p1],
                     fmaf(wT.z, cpz[p1], wA.w)));
            h0[i] = 0.f; h1v[i] = 0.f;
        }
        for (int k = 0; k < KK; k++) {
            const float4 kA = *(const float4*)&S.kd[p0][k][0];
            const float4 kB = *(const float4*)&S.kd[p1][k][0];
            #pragma unroll
            for (int i = 0; i < 8; i++) {
                float pa = fmaf(A0[i], kA.x, fmaf(A1[i], kA.y,
                            fmaf(A2[i], kA.z, t0[i])));
                h0[i] = fmaf(kA.w, fmaxf(pa, 0.f), h0[i]);
                float pbv = fmaf(A0[i], kB.x, fmaf(A1[i], kB.y,
                             fmaf(A2[i], kB.z, t1[i])));
                h1v[i] = fmaf(kB.w, fmaxf(pbv, 0.f), h1v[i]);
            }
        }
        #pragma unroll
        for (int i = 0; i < 8; i++) {
            const int c = lane + 32 * i;
            S.hb[c][p0] = h0[i];
            S.hb[c][p1] = h1v[i];
        }
    }
    __syncwarp();

    const int o1 = 2 * lane;

    // ---- layer 2: 256 -> 64, FFMA2, dup weights ----------------------------
    unsigned long long a1lo = 0, a1hi = 0, a2lo = 0, a2hi = 0;
    {
        const float* wrow = g_w2bd + o1 * 2;   // + lane*4 floats
        #pragma unroll 4
        for (int c = 0; c < HH; c++) {
            const ulonglong2 h2 = *(const ulonglong2*)&S.hb[c][0];
            const ulonglong2 w2 = *(const ulonglong2*)(wrow + c * 2 * CC);
            FMA2(a1lo, w2.x, h2.x); FMA2(a1hi, w2.x, h2.y);
            FMA2(a2lo, w2.y, h2.x); FMA2(a2hi, w2.y, h2.y);
        }
    }
    float pfx[4], pfy[4];
    UNPK2(pfx[0], pfx[1], a1lo); UNPK2(pfx[2], pfx[3], a1hi);
    UNPK2(pfy[0], pfy[1], a2lo); UNPK2(pfy[2], pfy[3], a2hi);
    {
        const float2 bb2 = *(const float2*)(b2b + o1);
        #pragma unroll
        for (int p = 0; p < 4; p++) {
            pfx[p] = fmaf(bb2.x, ssum[p], pfx[p]);
            pfy[p] = fmaf(bb2.y, ssum[p], pfy[p]);
        }
    }

    // ---- close_feat + co_feature -------------------------------------------
    float cf0[4], cf1[4], co0[4], co1[4];
    #pragma unroll
    for (int p = 0; p < 4; p++) {
        const float2 f =
            *(const float2*)(feature + ((size_t)b * MM + ci[p]) * CC + o1);
        cf0[p] = f.x; cf1[p] = f.y; co0[p] = 0.f; co1[p] = 0.f;
    }
    for (int k = 0; k < KK; k++) {
        #pragma unroll
        for (int p = 0; p < 4; p++) {
            const float2 jw = *(const float2*)&S.jw[p][k][0];
            const int j = __float_as_int(jw.x);
            const float2 f =
                *(const float2*)(feature + ((size_t)b * MM + j) * CC + o1);
            co0[p] = fmaf(jw.y, f.x, co0[p]);
            co1[p] = fmaf(jw.y, f.y, co1[p]);
        }
    }

    *(float4*)&S.df[o1][0]          = make_float4(cf0[0], cf0[1], cf0[2], cf0[3]);
    *(float4*)&S.df[o1 + 1][0]      = make_float4(cf1[0], cf1[1], cf1[2], cf1[3]);
    *(float4*)&S.df[CC + o1][0]     = make_float4(co0[0], co0[1], co0[2], co0[3]);
    *(float4*)&S.df[CC + o1 + 1][0] = make_float4(co1[0], co1[1], co1[2], co1[3]);
    *(float4*)&S.df[2 * CC + o1][0]     = make_float4(pfx[0], pfx[1], pfx[2], pfx[3]);
    *(float4*)&S.df[2 * CC + o1 + 1][0] = make_float4(pfy[0], pfy[1], pfy[2], pfy[3]);
    __syncwarp();

    // ---- final MLP layer 1: 192 -> 64, BN folded + ReLU --------------------
    unsigned long long f1lo = 0, f1hi = 0, f2lo = 0, f2hi = 0;
    {
        const float* wrow = g_w1ad + o1 * 2;
        #pragma unroll 4
        for (int c = 0; c < 3 * CC; c++) {
            const ulonglong2 d2 = *(const ulonglong2*)&S.df[c][0];
            const ulonglong2 w2 = *(const ulonglong2*)(wrow + c * 2 * CC);
            FMA2(f1lo, w2.x, d2.x); FMA2(f1hi, w2.x, d2.y);
            FMA2(f2lo, w2.y, d2.x); FMA2(f2hi, w2.y, d2.y);
        }
    }
    {
        float ax[4], ay[4];
        UNPK2(ax[0], ax[1], f1lo); UNPK2(ax[2], ax[3], f1hi);
        UNPK2(ay[0], ay[1], f2lo); UNPK2(ay[2], ay[3], f2hi);
        const float2 s2 = *(const float2*)(g_f1s + o1);
        const float2 b2 = *(const float2*)(g_f1b + o1);
        float hx[4], hy[4];
        #pragma unroll
        for (int p = 0; p < 4; p++) {
            hx[p] = fmaxf(fmaf(ax[p], s2.x, b2.x), 0.f);
            hy[p] = fmaxf(fmaf(ay[p], s2.y, b2.y), 0.f);
        }
        *(float4*)&S.h1[o1][0]     = make_float4(hx[0], hx[1], hx[2], hx[3]);
        *(float4*)&S.h1[o1 + 1][0] = make_float4(hy[0], hy[1], hy[2], hy[3]);
    }
    __syncwarp();

    // ---- final MLP layer 2: 64 -> 64 ---------------------------------------
    unsigned long long r1lo = 0, r1hi = 0, r2lo = 0, r2hi = 0;
    {
        const float* wrow = g_w1bd + o1 * 2;
        #pragma unroll 4
        for (int c = 0; c < CC; c++) {
            const ulonglong2 h2 = *(const ulonglong2*)&S.h1[c][0];
            const ulonglong2 w2 = *(const ulonglong2*)(wrow + c * 2 * CC);
            FMA2(r1lo, w2.x, h2.x); FMA2(r1hi, w2.x, h2.y);
            FMA2(r2lo, w2.y, h2.x); FMA2(r2hi, w2.y, h2.y);
        }
    }
    {
        float rx[4], ry[4];
        UNPK2(rx[0], rx[1], r1lo); UNPK2(rx[2], rx[3], r1hi);
        UNPK2(ry[0], ry[1], r2lo); UNPK2(ry[2], ry[3], r2hi);
        const float2 bo = *(const float2*)(b1b + o1);
        #pragma unroll
        for (int p = 0; p < 4; p++) {
            *(float2*)(out + ((size_t)b * NN + n0 + p) * CC + o1) =
                make_float2(rx[p] + bo.x, ry[p] + bo.y);
        }
    }
}

// ---------------------------------------------------------------------------
extern "C" void kernel_launch(void* const* d_in, const int* in_sizes, int n_in,
                              void* d_out, int out_size)
{
    (void)in_sizes; (void)n_in; (void)out_size;
    const float* pcl       = (const float*)d_in[0];
    const float* pcl_noise = (const float*)d_in[1];
    const float* feature   = (const float*)d_in[2];
    const float* w2a  = (const float*)d_in[3];
    const float* b2a  = (const float*)d_in[4];
    const float* g2a  = (const float*)d_in[5];
    const float* bt2a = (const float*)d_in[6];
    const float* w2b  = (const float*)d_in[7];
    const float* b2b  = (const float*)d_in[8];
    const float* w1a  = (const float*)d_in[9];
    const float* b1a  = (const float*)d_in[10];
    const float* g1a  = (const float*)d_in[11];
    const float* bt1a = (const float*)d_in[12];
    const float* w1b  = (const float*)d_in[13];
    const float* b1b  = (const float*)d_in[14];
    float* out = (float*)d_out;

    prep_kernel<<<64, 256>>>(w2a, b2a, g2a, bt2a, w2b, w1a, b1a, g1a, bt1a, w1b);
    nn_part_kernel<<<dim3(NN / 128, NCHUNK, BB), 128>>>(pcl, pcl_noise);
    knn_kernel<<<dim3(MM / 16, BB), 128>>>(pcl);
    fused_kernel<<<(BB * NN) / 16, 128>>>(
        pcl, pcl_noise, feature, b2b, b1b, out);
}

// round 6
// speedup vs baseline: 6.3765x; 1.1993x over previous
#include <cuda_runtime.h>
#include <math.h>

#define BB  2
#define NN  8192
#define MM  4096
#define CC  64
#define KK  15      // K-1 neighbors actually used
#define HH  256
#define NCHUNK 8
#define CHM (MM / NCHUNK)   // 512

// Scratch (allocation-free rule: __device__ globals)
__device__ unsigned long long g_nn_part[BB * NCHUNK * NN];
__device__ int   g_knn[BB * MM * KK];
// prepped weights
__device__ float g_l1A[HH * 4];          // [c][{A0,A1,A2,B}]  (BN-folded)
__device__ float g_l1T[HH * 4];          // [c][{A3,A4,A5,0}]  (BN-folded)
__device__ float g_wt2b[HH * CC];        // [c][o]
__device__ float g_wt1a[3 * CC * CC];    // [c][o]
__device__ float g_wt1b[CC * CC];        // [c][o]
__device__ float g_f1s[CC];              // g1a*invs
__device__ float g_f1b[CC];              // b1a*g' + bt1a

#define FMA2(acc, a, b) \
    asm("fma.rn.f32x2 %0, %1, %2, %0;" : "+l"(acc) : "l"(a), "l"(b))
#define UNPK2(lo, hi, v) \
    asm("mov.b64 {%0, %1}, %2;" : "=f"(lo), "=f"(hi) : "l"(v))
#define DUP2(out, v) \
    asm("mov.b64 %0, {%1, %1};" : "=l"(out) : "f"(v))

static __device__ __forceinline__ unsigned long long packkey(float d, int idx) {
    return ((unsigned long long)__float_as_uint(d) << 32) | (unsigned)idx;
}

// ---------------------------------------------------------------------------
// Kernel P: fold BN + transpose weight prep.
// ---------------------------------------------------------------------------
__global__ __launch_bounds__(256) void prep_kernel(
    const float* __restrict__ w2a, const float* __restrict__ b2a,
    const float* __restrict__ g2a, const float* __restrict__ bt2a,
    const float* __restrict__ w2b,
    const float* __restrict__ w1a, const float* __restrict__ b1a,
    const float* __restrict__ g1a, const float* __restrict__ bt1a,
    const float* __restrict__ w1b)
{
    const float invs = rsqrtf(1.0f + 1e-5f);
    const int t = blockIdx.x * 256 + threadIdx.x;
    const int stride = gridDim.x * 256;

    for (int c = t; c < HH; c += stride) {
        const float gp = g2a[c] * invs;
        g_l1A[c * 4 + 0] = w2a[c * 6 + 0] * gp;
        g_l1A[c * 4 + 1] = w2a[c * 6 + 1] * gp;
        g_l1A[c * 4 + 2] = w2a[c * 6 + 2] * gp;
        g_l1A[c * 4 + 3] = b2a[c] * gp + bt2a[c];
        g_l1T[c * 4 + 0] = w2a[c * 6 + 3] * gp;
        g_l1T[c * 4 + 1] = w2a[c * 6 + 4] * gp;
        g_l1T[c * 4 + 2] = w2a[c * 6 + 5] * gp;
        g_l1T[c * 4 + 3] = 0.f;
    }
    for (int idx = t; idx < HH * CC; idx += stride) {
        int c = idx / CC, o = idx - c * CC;
        g_wt2b[idx] = w2b[o * HH + c];
    }
    for (int idx = t; idx < 3 * CC * CC; idx += stride) {
        int c = idx / CC, o = idx - c * CC;
        g_wt1a[idx] = w1a[o * (3 * CC) + c];
    }
    for (int idx = t; idx < CC * CC; idx += stride) {
        int c = idx / CC, o = idx - c * CC;
        g_wt1b[idx] = w1b[o * CC + c];
    }
    for (int o = t; o < CC; o += stride) {
        const float s = g1a[o] * invs;
        g_f1s[o] = s;
        g_f1b[o] = b1a[o] * s + bt1a[o];
    }
}

// ---------------------------------------------------------------------------
// Kernel A: partial argmin over a 512-candidate chunk of pcl, per noisy pt.
// ---------------------------------------------------------------------------
__global__ __launch_bounds__(128) void nn_part_kernel(
    const float* __restrict__ pcl, const float* __restrict__ pcl_noise)
{
    const int b = blockIdx.z;
    const int chunk = blockIdx.y;
    const int n = blockIdx.x * 128 + threadIdx.x;
    const float* pb = pcl + (size_t)b * MM * 3 + (size_t)chunk * CHM * 3;

    const float qx = pcl_noise[((size_t)b * NN + n) * 3 + 0];
    const float qy = pcl_noise[((size_t)b * NN + n) * 3 + 1];
    const float qz = pcl_noise[((size_t)b * NN + n) * 3 + 2];

    __shared__ float sp[3 * CHM];
    for (int i = threadIdx.x; i < (3 * CHM) / 4; i += 128)
        ((float4*)sp)[i] = ((const float4*)pb)[i];
    __syncthreads();

    float best = 3.4e38f;
    int   bi   = 0;

    const float4* sp4 = (const float4*)sp;
    #pragma unroll 4
    for (int j = 0; j < CHM; j += 4) {
        const int f4 = (j * 3) >> 2;
        float4 a = sp4[f4], c1 = sp4[f4 + 1], c2 = sp4[f4 + 2];
        float dx, dy, dz;
        dx = a.x - qx;  dy = a.y - qy;  dz = a.z - qz;
        float d0 = dx * dx + dy * dy + dz * dz;
        dx = a.w - qx;  dy = c1.x - qy; dz = c1.y - qz;
        float d1 = dx * dx + dy * dy + dz * dz;
        dx = c1.z - qx; dy = c1.w - qy; dz = c2.x - qz;
        float d2 = dx * dx + dy * dy + dz * dz;
        dx = c2.y - qx; dy = c2.z - qy; dz = c2.w - qz;
        float d3 = dx * dx + dy * dy + dz * dz;

        if (d0 < best) { best = d0; bi = j;     }
        if (d1 < best) { best = d1; bi = j + 1; }
        if (d2 < best) { best = d2; bi = j + 2; }
        if (d3 < best) { best = d3; bi = j + 3; }
    }
    g_nn_part[((size_t)b * NCHUNK + chunk) * NN + n] =
        packkey(best, chunk * CHM + bi);
}

// ---------------------------------------------------------------------------
// Kernel B: self-KNN, ONE WARP PER QUERY (8 warps/block share the tile).
// Distributed sorted top-16 in lanes 0..15 (u64 keys). Float prefilter;
// exact u64 key compare in the (rare, ~105x/query) insert path. 4x the
// warps of the old layout -> insert latency chains hidden by occupancy.
// ---------------------------------------------------------------------------
__global__ __launch_bounds__(256) void knn_kernel(const float* __restrict__ pcl)
{
    const int b = blockIdx.y;
    const int wrp  = threadIdx.x >> 5;
    const int lane = threadIdx.x & 31;
    const float* pb = pcl + (size_t)b * MM * 3;
    const unsigned FULL = 0xffffffffu;

    __shared__ float sx[MM], sy[MM], sz[MM];
    for (int i = threadIdx.x; i < 3 * MM; i += 256) {
        float v = pb[i];
        int m = i / 3, c = i - 3 * m;
        if (c == 0) sx[m] = v; else if (c == 1) sy[m] = v; else sz[m] = v;
    }
    __syncthreads();

    const int m = blockIdx.x * 8 + wrp;
    const float qx = sx[m], qy = sy[m], qz = sz[m];

    unsigned long long key = 0xffffffffffffffffull;   // lanes 0..15 = list
    unsigned long long kmk = 0xffffffffffffffffull;
    float kmd = 3.4e38f;

    for (int t = 0; t < MM / 32; t++) {
        const int j = lane + 32 * t;
        const float dx = sx[j] - qx, dy = sy[j] - qy, dz = sz[j] - qz;
        const float dc = dx * dx + dy * dy + dz * dz;

        unsigned pend = __ballot_sync(FULL, dc <= kmd);
        while (pend) {
            const int src = __ffs(pend) - 1;
            pend &= pend - 1;
            const float dcc = __shfl_sync(FULL, dc, src);
            const unsigned long long kc = packkey(dcc, src + 32 * t);
            if (kc < kmk) {
                const unsigned bal = __ballot_sync(FULL, key > kc) & 0xFFFFu;
                const int p = __ffs(bal) - 1;
                const unsigned long long up = __shfl_up_sync(FULL, key, 1);
                if (lane == p)      key = kc;
                else if (lane > p)  key = up;
                kmk = __shfl_sync(FULL, key, 15);
                kmd = __uint_as_float((unsigned)(kmk >> 32));
            }
        }
    }

    // rank 0 is the self point; emit ranks 1..15
    const int base = (b * MM + m) * KK;
    if (lane >= 1 && lane <= KK)
        g_knn[base + lane - 1] = (int)(key & 0xffffffffu);
}

// ---------------------------------------------------------------------------
// Kernel C: fused NN-merge + gather + MLPs. One warp per 4 points.
// Weights non-duplicated [c][o]: LDG.64 (2 lines/warp) + mov.b64 {v,v}
// packing feeds FFMA2 -> fewer L1 wavefronts, weights L1-resident.
// ---------------------------------------------------------------------------
struct __align__(16) WarpSm {
    float kd[4][16][4];   // [p][k][dx,dy,dz,lw]
    float jw[4][16][2];   // [p][k][jk(bits), lw]
    float hb[HH][4];      // hbar, channel-major
    float df[3 * CC][4];  // df, channel-major
    float h1[CC][4];
};

__global__ __launch_bounds__(128) void fused_kernel(
    const float* __restrict__ pcl,  const float* __restrict__ pcl_noise,
    const float* __restrict__ feature,
    const float* __restrict__ b2b,  const float* __restrict__ b1b,
    float* __restrict__ out)
{
    const int wrp  = threadIdx.x >> 5;
    const int lane = threadIdx.x & 31;
    const int pt0  = (blockIdx.x * 4 + wrp) * 4;   // 4 consecutive points
    const int b    = pt0 >> 13;
    const int n0   = pt0 & (NN - 1);
    const unsigned FULL = 0xffffffffu;

    __shared__ WarpSm sm[4];
    WarpSm& S = sm[wrp];

    // ---- distributed NN-merge: lane = p*8 + chunk --------------------------
    int ci[4];
    {
        const int p = lane >> 3, c = lane & 7;
        unsigned long long k =
            g_nn_part[((size_t)b * NCHUNK + c) * NN + (n0 + p)];
        unsigned long long o;
        o = __shfl_xor_sync(FULL, k, 4); if (o < k) k = o;
        o = __shfl_xor_sync(FULL, k, 2); if (o < k) k = o;
        o = __shfl_xor_sync(FULL, k, 1); if (o < k) k = o;
        #pragma unroll
        for (int p2 = 0; p2 < 4; p2++)
            ci[p2] = (int)(__shfl_sync(FULL, k, p2 * 8) & 0xffffffffu);
    }

    // ---- query coords (3x LDG.128 broadcast) + close points ----------------
    float qx[4], qy[4], qz[4], cpx[4], cpy[4], cpz[4];
    {
        const float4* q4 =
            (const float4*)(pcl_noise + ((size_t)b * NN + n0) * 3);
        const float4 Q0 = q4[0], Q1 = q4[1], Q2 = q4[2];
        qx[0] = Q0.x; qy[0] = Q0.y; qz[0] = Q0.z;
        qx[1] = Q0.w; qy[1] = Q1.x; qz[1] = Q1.y;
        qx[2] = Q1.z; qy[2] = Q1.w; qz[2] = Q2.x;
        qx[3] = Q2.y; qy[3] = Q2.z; qz[3] = Q2.w;
        #pragma unroll
        for (int p = 0; p < 4; p++) {
            const float* cp = pcl + ((size_t)b * MM + ci[p]) * 3;
            cpx[p] = cp[0]; cpy[p] = cp[1]; cpz[p] = cp[2];
        }
    }

    // ---- neighbors: lane k owns neighbor k of each point -------------------
    float ssum[4];
    #pragma unroll
    for (int p = 0; p < 4; p++) {
        int jk = 0; float dx = 0.f, dy = 0.f, dz = 0.f, e = 0.f;
        if (lane < KK) {
            jk = g_knn[(b * MM + ci[p]) * KK + lane];
            const float* pp = pcl + ((size_t)b * MM + jk) * 3;
            dx = pp[0] - qx[p]; dy = pp[1] - qy[p]; dz = pp[2] - qz[p];
            e = expf(-10.0f * sqrtf(dx * dx + dy * dy + dz * dz));
        }
        float Sv = e;
        #pragma unroll
        for (int o = 16; o; o >>= 1) Sv += __shfl_xor_sync(FULL, Sv, o);
        const float lw = e / (Sv + 1e-7f);
        ssum[p] = Sv / (Sv + 1e-7f);
        if (lane < KK) {
            *(float4*)&S.kd[p][lane][0] = make_float4(dx, dy, dz, lw);
            *(float2*)&S.jw[p][lane][0] =
                make_float2(__int_as_float(jk), lw);
        }
    }
    __syncwarp();

    // ---- layer 1 (6 -> 256, BN folded), 2 passes of 2 points ---------------
    #pragma unroll
    for (int s = 0; s < 2; s++) {
        const int p0 = 2 * s, p1 = 2 * s + 1;
        float A0[8], A1[8], A2[8], t0[8], t1[8], h0[8], h1v[8];
        #pragma unroll
        for (int i = 0; i < 8; i++) {
            const int c = lane + 32 * i;
            const float4 wA = *(const float4*)&g_l1A[c * 4];
            const float4 wT = *(const float4*)&g_l1T[c * 4];
            A0[i] = wA.x; A1[i] = wA.y; A2[i] = wA.z;
            t0[i] = fmaf(wT.x, cpx[p0], fmaf(wT.y, cpy[p0],
                     fmaf(wT.z, cpz[p0], wA.w)));
            t1[i] = fmaf(wT.x, cpx[p1], fmaf(wT.y, cpy[p1],
                     fmaf(wT.z, cpz[p1], wA.w)));
            h0[i] = 0.f; h1v[i] = 0.f;
        }
        for (int k = 0; k < KK; k++) {
            const float4 kA = *(const float4*)&S.kd[p0][k][0];
            const float4 kB = *(const float4*)&S.kd[p1][k][0];
            #pragma unroll
            for (int i = 0; i < 8; i++) {
                float pa = fmaf(A0[i], kA.x, fmaf(A1[i], kA.y,
                            fmaf(A2[i], kA.z, t0[i])));
                h0[i] = fmaf(kA.w, fmaxf(pa, 0.f), h0[i]);
                float pbv = fmaf(A0[i], kB.x, fmaf(A1[i], kB.y,
                             fmaf(A2[i], kB.z, t1[i])));
                h1v[i] = fmaf(kB.w, fmaxf(pbv, 0.f), h1v[i]);
            }
        }
        #pragma unroll
        for (int i = 0; i < 8; i++) {
            const int c = lane + 32 * i;
            S.hb[c][p0] = h0[i];
            S.hb[c][p1] = h1v[i];
        }
    }
    __syncwarp();

    const int o1 = 2 * lane;

    // ---- layer 2: 256 -> 64, FFMA2, {v,v}-packed weights -------------------
    unsigned long long a1lo = 0, a1hi = 0, a2lo = 0, a2hi = 0;
    {
        const float* wrow = g_wt2b + o1;
        #pragma unroll 4
        for (int c = 0; c < HH; c++) {
            const ulonglong2 h2 = *(const ulonglong2*)&S.hb[c][0];
            const float2 wv = *(const float2*)(wrow + c * CC);
            unsigned long long wx, wy;
            DUP2(wx, wv.x); DUP2(wy, wv.y);
            FMA2(a1lo, wx, h2.x); FMA2(a1hi, wx, h2.y);
            FMA2(a2lo, wy, h2.x); FMA2(a2hi, wy, h2.y);
        }
    }
    float pfx[4], pfy[4];
    UNPK2(pfx[0], pfx[1], a1lo); UNPK2(pfx[2], pfx[3], a1hi);
    UNPK2(pfy[0], pfy[1], a2lo); UNPK2(pfy[2], pfy[3], a2hi);
    {
        const float2 bb2 = *(const float2*)(b2b + o1);
        #pragma unroll
        for (int p = 0; p < 4; p++) {
            pfx[p] = fmaf(bb2.x, ssum[p], pfx[p]);
            pfy[p] = fmaf(bb2.y, ssum[p], pfy[p]);
        }
    }

    // ---- close_feat + co_feature -------------------------------------------
    float cf0[4], cf1[4], co0[4], co1[4];
    #pragma unroll
    for (int p = 0; p < 4; p++) {
        const float2 f =
            *(const float2*)(feature + ((size_t)b * MM + ci[p]) * CC + o1);
        cf0[p] = f.x; cf1[p] = f.y; co0[p] = 0.f; co1[p] = 0.f;
    }
    for (int k = 0; k < KK; k++) {
        #pragma unroll
        for (int p = 0; p < 4; p++) {
            const float2 jw = *(const float2*)&S.jw[p][k][0];
            const int j = __float_as_int(jw.x);
            const float2 f =
                *(const float2*)(feature + ((size_t)b * MM + j) * CC + o1);
            co0[p] = fmaf(jw.y, f.x, co0[p]);
            co1[p] = fmaf(jw.y, f.y, co1[p]);
        }
    }

    *(float4*)&S.df[o1][0]          = make_float4(cf0[0], cf0[1], cf0[2], cf0[3]);
    *(float4*)&S.df[o1 + 1][0]      = make_float4(cf1[0], cf1[1], cf1[2], cf1[3]);
    *(float4*)&S.df[CC + o1][0]     = make_float4(co0[0], co0[1], co0[2], co0[3]);
    *(float4*)&S.df[CC + o1 + 1][0] = make_float4(co1[0], co1[1], co1[2], co1[3]);
    *(float4*)&S.df[2 * CC + o1][0]     = make_float4(pfx[0], pfx[1], pfx[2], pfx[3]);
    *(float4*)&S.df[2 * CC + o1 + 1][0] = make_float4(pfy[0], pfy[1], pfy[2], pfy[3]);
    __syncwarp();

    // ---- final MLP layer 1: 192 -> 64, BN folded + ReLU --------------------
    unsigned long long f1lo = 0, f1hi = 0, f2lo = 0, f2hi = 0;
    {
        const float* wrow = g_wt1a + o1;
        #pragma unroll 4
        for (int c = 0; c < 3 * CC; c++) {
            const ulonglong2 d2 = *(const ulonglong2*)&S.df[c][0];
            const float2 wv = *(const float2*)(wrow + c * CC);
            unsigned long long wx, wy;
            DUP2(wx, wv.x); DUP2(wy, wv.y);
            FMA2(f1lo, wx, d2.x); FMA2(f1hi, wx, d2.y);
            FMA2(f2lo, wy, d2.x); FMA2(f2hi, wy, d2.y);
        }
    }
    {
        float ax[4], ay[4];
        UNPK2(ax[0], ax[1], f1lo); UNPK2(ax[2], ax[3], f1hi);
        UNPK2(ay[0], ay[1], f2lo); UNPK2(ay[2], ay[3], f2hi);
        const float2 s2 = *(const float2*)(g_f1s + o1);
        const float2 b2 = *(const float2*)(g_f1b + o1);
        float hx[4], hy[4];
        #pragma unroll
        for (int p = 0; p < 4; p++) {
            hx[p] = fmaxf(fmaf(ax[p], s2.x, b2.x), 0.f);
            hy[p] = fmaxf(fmaf(ay[p], s2.y, b2.y), 0.f);
        }
        *(float4*)&S.h1[o1][0]     = make_float4(hx[0], hx[1], hx[2], hx[3]);
        *(float4*)&S.h1[o1 + 1][0] = make_float4(hy[0], hy[1], hy[2], hy[3]);
    }
    __syncwarp();

    // ---- final MLP layer 2: 64 -> 64 ---------------------------------------
    unsigned long long r1lo = 0, r1hi = 0, r2lo = 0, r2hi = 0;
    {
        const float* wrow = g_wt1b + o1;
        #pragma unroll 4
        for (int c = 0; c < CC; c++) {
            const ulonglong2 h2 = *(const ulonglong2*)&S.h1[c][0];
            const float2 wv = *(const float2*)(wrow + c * CC);
            unsigned long long wx, wy;
            DUP2(wx, wv.x); DUP2(wy, wv.y);
            FMA2(r1lo, wx, h2.x); FMA2(r1hi, wx, h2.y);
            FMA2(r2lo, wy, h2.x); FMA2(r2hi, wy, h2.y);
        }
    }
    {
        float rx[4], ry[4];
        UNPK2(rx[0], rx[1], r1lo); UNPK2(rx[2], rx[3], r1hi);
        UNPK2(ry[0], ry[1], r2lo); UNPK2(ry[2], ry[3], r2hi);
        const float2 bo = *(const float2*)(b1b + o1);
        #pragma unroll
        for (int p = 0; p < 4; p++) {
            *(float2*)(out + ((size_t)b * NN + n0 + p) * CC + o1) =
                make_float2(rx[p] + bo.x, ry[p] + bo.y);
        }
    }
}

// ---------------------------------------------------------------------------
extern "C" void kernel_launch(void* const* d_in, const int* in_sizes, int n_in,
                              void* d_out, int out_size)
{
    (void)in_sizes; (void)n_in; (void)out_size;
    const float* pcl       = (const float*)d_in[0];
    const float* pcl_noise = (const float*)d_in[1];
    const float* feature   = (const float*)d_in[2];
    const float* w2a  = (const float*)d_in[3];
    const float* b2a  = (const float*)d_in[4];
    const float* g2a  = (const float*)d_in[5];
    const float* bt2a = (const float*)d_in[6];
    const float* w2b  = (const float*)d_in[7];
    const float* b2b  = (const float*)d_in[8];
    const float* w1a  = (const float*)d_in[9];
    const float* b1a  = (const float*)d_in[10];
    const float* g1a  = (const float*)d_in[11];
    const float* bt1a = (const float*)d_in[12];
    const float* w1b  = (const float*)d_in[13];
    const float* b1b  = (const float*)d_in[14];
    float* out = (float*)d_out;

    prep_kernel<<<64, 256>>>(w2a, b2a, g2a, bt2a, w2b, w1a, b1a, g1a, bt1a, w1b);
    nn_part_kernel<<<dim3(NN / 128, NCHUNK, BB), 128>>>(pcl, pcl_noise);
    knn_kernel<<<dim3(MM / 8, BB), 256>>>(pcl);
    fused_kernel<<<(BB * NN) / 16, 128>>>(
        pcl, pcl_noise, feature, b2b, b1b, out);
}

// round 7
// speedup vs baseline: 6.6365x; 1.0408x over previous
#include <cuda_runtime.h>
#include <math.h>

#define BB  2
#define NN  8192
#define MM  4096
#define CC  64
#define KK  15      // K-1 neighbors actually used
#define HH  256
#define NCHUNK 8
#define CHM (MM / NCHUNK)   // 512

// Scratch (allocation-free rule: __device__ globals)
__device__ unsigned long long g_nn_part[BB * NCHUNK * NN];
__device__ int   g_knn[BB * MM * KK];
// prepped weights
__device__ float g_l1A[HH * 4];          // [c][{A0,A1,A2,B}]  (BN-folded)
__device__ float g_l1T[HH * 4];          // [c][{A3,A4,A5,0}]  (BN-folded)
__device__ float g_wt2b[HH * CC];        // [c][o]
__device__ float g_wt1a[3 * CC * CC];    // [c][o]
__device__ float g_wt1b[CC * CC];        // [c][o]
__device__ float g_f1s[CC];              // g1a*invs
__device__ float g_f1b[CC];              // b1a*g' + bt1a

#define FMA2(acc, a, b) \
    asm("fma.rn.f32x2 %0, %1, %2, %0;" : "+l"(acc) : "l"(a), "l"(b))
#define ADD2(acc, a) \
    asm("add.rn.f32x2 %0, %0, %1;" : "+l"(acc) : "l"(a))
#define UNPK2(lo, hi, v) \
    asm("mov.b64 {%0, %1}, %2;" : "=f"(lo), "=f"(hi) : "l"(v))
#define DUP2(out, v) \
    asm("mov.b64 %0, {%1, %1};" : "=l"(out) : "f"(v))

static __device__ __forceinline__ unsigned long long packkey(float d, int idx) {
    return ((unsigned long long)__float_as_uint(d) << 32) | (unsigned)idx;
}

// ---------------------------------------------------------------------------
// Kernel P: fold BN + transpose weight prep.
// ---------------------------------------------------------------------------
__global__ __launch_bounds__(256) void prep_kernel(
    const float* __restrict__ w2a, const float* __restrict__ b2a,
    const float* __restrict__ g2a, const float* __restrict__ bt2a,
    const float* __restrict__ w2b,
    const float* __restrict__ w1a, const float* __restrict__ b1a,
    const float* __restrict__ g1a, const float* __restrict__ bt1a,
    const float* __restrict__ w1b)
{
    const float invs = rsqrtf(1.0f + 1e-5f);
    const int t = blockIdx.x * 256 + threadIdx.x;
    const int stride = gridDim.x * 256;

    for (int c = t; c < HH; c += stride) {
        const float gp = g2a[c] * invs;
        g_l1A[c * 4 + 0] = w2a[c * 6 + 0] * gp;
        g_l1A[c * 4 + 1] = w2a[c * 6 + 1] * gp;
        g_l1A[c * 4 + 2] = w2a[c * 6 + 2] * gp;
        g_l1A[c * 4 + 3] = b2a[c] * gp + bt2a[c];
        g_l1T[c * 4 + 0] = w2a[c * 6 + 3] * gp;
        g_l1T[c * 4 + 1] = w2a[c * 6 + 4] * gp;
        g_l1T[c * 4 + 2] = w2a[c * 6 + 5] * gp;
        g_l1T[c * 4 + 3] = 0.f;
    }
    for (int idx = t; idx < HH * CC; idx += stride) {
        int c = idx / CC, o = idx - c * CC;
        g_wt2b[idx] = w2b[o * HH + c];
    }
    for (int idx = t; idx < 3 * CC * CC; idx += stride) {
        int c = idx / CC, o = idx - c * CC;
        g_wt1a[idx] = w1a[o * (3 * CC) + c];
    }
    for (int idx = t; idx < CC * CC; idx += stride) {
        int c = idx / CC, o = idx - c * CC;
        g_wt1b[idx] = w1b[o * CC + c];
    }
    for (int o = t; o < CC; o += stride) {
        const float s = g1a[o] * invs;
        g_f1s[o] = s;
        g_f1b[o] = b1a[o] * s + bt1a[o];
    }
}

// ---------------------------------------------------------------------------
// Kernel A: partial argmin over a 512-candidate chunk of pcl, per noisy pt.
// ---------------------------------------------------------------------------
__global__ __launch_bounds__(128) void nn_part_kernel(
    const float* __restrict__ pcl, const float* __restrict__ pcl_noise)
{
    const int b = blockIdx.z;
    const int chunk = blockIdx.y;
    const int n = blockIdx.x * 128 + threadIdx.x;
    const float* pb = pcl + (size_t)b * MM * 3 + (size_t)chunk * CHM * 3;

    const float qx = pcl_noise[((size_t)b * NN + n) * 3 + 0];
    const float qy = pcl_noise[((size_t)b * NN + n) * 3 + 1];
    const float qz = pcl_noise[((size_t)b * NN + n) * 3 + 2];

    __shared__ float sp[3 * CHM];
    for (int i = threadIdx.x; i < (3 * CHM) / 4; i += 128)
        ((float4*)sp)[i] = ((const float4*)pb)[i];
    __syncthreads();

    float best = 3.4e38f;
    int   bi   = 0;

    const float4* sp4 = (const float4*)sp;
    #pragma unroll 4
    for (int j = 0; j < CHM; j += 4) {
        const int f4 = (j * 3) >> 2;
        float4 a = sp4[f4], c1 = sp4[f4 + 1], c2 = sp4[f4 + 2];
        float dx, dy, dz;
        dx = a.x - qx;  dy = a.y - qy;  dz = a.z - qz;
        float d0 = dx * dx + dy * dy + dz * dz;
        dx = a.w - qx;  dy = c1.x - qy; dz = c1.y - qz;
        float d1 = dx * dx + dy * dy + dz * dz;
        dx = c1.z - qx; dy = c1.w - qy; dz = c2.x - qz;
        float d2 = dx * dx + dy * dy + dz * dz;
        dx = c2.y - qx; dy = c2.z - qy; dz = c2.w - qz;
        float d3 = dx * dx + dy * dy + dz * dz;

        if (d0 < best) { best = d0; bi = j;     }
        if (d1 < best) { best = d1; bi = j + 1; }
        if (d2 < best) { best = d2; bi = j + 2; }
        if (d3 < best) { best = d3; bi = j + 3; }
    }
    g_nn_part[((size_t)b * NCHUNK + chunk) * NN + n] =
        packkey(best, chunk * CHM + bi);
}

// ---------------------------------------------------------------------------
// Kernel B: self-KNN, one warp per query, 512-thread blocks (16 warps share
// the 48KB tile; 4 blocks/SM -> 64 warps/SM to hide insert latency chains).
// ---------------------------------------------------------------------------
__global__ __launch_bounds__(512) void knn_kernel(const float* __restrict__ pcl)
{
    const int b = blockIdx.y;
    const int wrp  = threadIdx.x >> 5;
    const int lane = threadIdx.x & 31;
    const float* pb = pcl + (size_t)b * MM * 3;
    const unsigned FULL = 0xffffffffu;

    __shared__ float sx[MM], sy[MM], sz[MM];
    for (int i = threadIdx.x; i < 3 * MM; i += 512) {
        float v = pb[i];
        int m = i / 3, c = i - 3 * m;
        if (c == 0) sx[m] = v; else if (c == 1) sy[m] = v; else sz[m] = v;
    }
    __syncthreads();

    const int m = blockIdx.x * 16 + wrp;
    const float qx = sx[m], qy = sy[m], qz = sz[m];

    unsigned long long key = 0xffffffffffffffffull;   // lanes 0..15 = list
    unsigned long long kmk = 0xffffffffffffffffull;
    float kmd = 3.4e38f;

    for (int t = 0; t < MM / 32; t++) {
        const int j = lane + 32 * t;
        const float dx = sx[j] - qx, dy = sy[j] - qy, dz = sz[j] - qz;
        const float dc = dx * dx + dy * dy + dz * dz;

        unsigned pend = __ballot_sync(FULL, dc <= kmd);
        while (pend) {
            const int src = __ffs(pend) - 1;
            pend &= pend - 1;
            const float dcc = __shfl_sync(FULL, dc, src);
            const unsigned long long kc = packkey(dcc, src + 32 * t);
            if (kc < kmk) {
                const unsigned bal = __ballot_sync(FULL, key > kc) & 0xFFFFu;
                const int p = __ffs(bal) - 1;
                const unsigned long long up = __shfl_up_sync(FULL, key, 1);
                if (lane == p)      key = kc;
                else if (lane > p)  key = up;
                kmk = __shfl_sync(FULL, key, 15);
                kmd = __uint_as_float((unsigned)(kmk >> 32));
            }
        }
    }

    // rank 0 is the self point; emit ranks 1..15
    const int base = (b * MM + m) * KK;
    if (lane >= 1 && lane <= KK)
        g_knn[base + lane - 1] = (int)(key & 0xffffffffu);
}

// ---------------------------------------------------------------------------
// Kernel C: fused NN-merge + gather + MLPs. One warp per 2 POINTS (8192
// warps -> 55/SM, latency-hiding). Smem unioned across sequential phases
// (hb overlaps df+h1): 2.8KB/warp. Split even/odd accumulator chains.
// ---------------------------------------------------------------------------
struct __align__(16) WarpSm {
    float kd[2][16][4];   // [p][k][dx,dy,dz,lw]
    float jw[2][16][2];   // [p][k][jk(bits), lw]
    union {
        float hb[HH][2];              // 2048 B, phase 1-2
        struct {
            float df[3 * CC][2];      // 1536 B, phase 3
            float h1[CC][2];          //  512 B, phase 4
        } s;
    } u;
};

__global__ __launch_bounds__(128) void fused_kernel(
    const float* __restrict__ pcl,  const float* __restrict__ pcl_noise,
    const float* __restrict__ feature,
    const float* __restrict__ b2b,  const float* __restrict__ b1b,
    float* __restrict__ out)
{
    const int wrp  = threadIdx.x >> 5;
    const int lane = threadIdx.x & 31;
    const int pt0  = (blockIdx.x * 4 + wrp) * 2;   // 2 consecutive points
    const int b    = pt0 >> 13;
    const int n0   = pt0 & (NN - 1);
    const unsigned FULL = 0xffffffffu;

    __shared__ WarpSm sm[4];
    WarpSm& S = sm[wrp];

    // ---- distributed NN-merge: lanes 0..15, lane = p*8 + chunk -------------
    int ci[2];
    {
        const int p = (lane >> 3) & 1, c = lane & 7;
        unsigned long long k =
            g_nn_part[((size_t)b * NCHUNK + c) * NN + (n0 + p)];
        unsigned long long o;
        o = __shfl_xor_sync(FULL, k, 4); if (o < k) k = o;
        o = __shfl_xor_sync(FULL, k, 2); if (o < k) k = o;
        o = __shfl_xor_sync(FULL, k, 1); if (o < k) k = o;
        ci[0] = (int)(__shfl_sync(FULL, k, 0) & 0xffffffffu);
        ci[1] = (int)(__shfl_sync(FULL, k, 8) & 0xffffffffu);
    }

    // ---- query coords + close points ---------------------------------------
    float qx[2], qy[2], qz[2], cpx[2], cpy[2], cpz[2];
    {
        const float2* q2 =
            (const float2*)(pcl_noise + ((size_t)b * NN + n0) * 3);
        const float2 Q0 = q2[0], Q1 = q2[1], Q2 = q2[2];
        qx[0] = Q0.x; qy[0] = Q0.y; qz[0] = Q1.x;
        qx[1] = Q1.y; qy[1] = Q2.x; qz[1] = Q2.y;
        #pragma unroll
        for (int p = 0; p < 2; p++) {
            const float* cp = pcl + ((size_t)b * MM + ci[p]) * 3;
            cpx[p] = cp[0]; cpy[p] = cp[1]; cpz[p] = cp[2];
        }
    }

    // ---- neighbors: lane k owns neighbor k of each point -------------------
    float ssum[2];
    #pragma unroll
    for (int p = 0; p < 2; p++) {
        int jk = 0; float dx = 0.f, dy = 0.f, dz = 0.f, e = 0.f;
        if (lane < KK) {
            jk = g_knn[(b * MM + ci[p]) * KK + lane];
            const float* pp = pcl + ((size_t)b * MM + jk) * 3;
            dx = pp[0] - qx[p]; dy = pp[1] - qy[p]; dz = pp[2] - qz[p];
            e = expf(-10.0f * sqrtf(dx * dx + dy * dy + dz * dz));
        }
        float Sv = e;
        #pragma unroll
        for (int o = 16; o; o >>= 1) Sv += __shfl_xor_sync(FULL, Sv, o);
        const float lw = e / (Sv + 1e-7f);
        ssum[p] = Sv / (Sv + 1e-7f);
        if (lane < KK) {
            *(float4*)&S.kd[p][lane][0] = make_float4(dx, dy, dz, lw);
            *(float2*)&S.jw[p][lane][0] =
                make_float2(__int_as_float(jk), lw);
        }
    }
    __syncwarp();

    // ---- layer 1 (6 -> 256, BN folded), both points ------------------------
    {
        float A0[8], A1[8], A2[8], t0[8], t1[8], h0[8], h1v[8];
        #pragma unroll
        for (int i = 0; i < 8; i++) {
            const int c = lane + 32 * i;
            const float4 wA = *(const float4*)&g_l1A[c * 4];
            const float4 wT = *(const float4*)&g_l1T[c * 4];
            A0[i] = wA.x; A1[i] = wA.y; A2[i] = wA.z;
            t0[i] = fmaf(wT.x, cpx[0], fmaf(wT.y, cpy[0],
                     fmaf(wT.z, cpz[0], wA.w)));
            t1[i] = fmaf(wT.x, cpx[1], fmaf(wT.y, cpy[1],
                     fmaf(wT.z, cpz[1], wA.w)));
            h0[i] = 0.f; h1v[i] = 0.f;
        }
        for (int k = 0; k < KK; k++) {
            const float4 kA = *(const float4*)&S.kd[0][k][0];
            const float4 kB = *(const float4*)&S.kd[1][k][0];
            #pragma unroll
            for (int i = 0; i < 8; i++) {
                float pa = fmaf(A0[i], kA.x, fmaf(A1[i], kA.y,
                            fmaf(A2[i], kA.z, t0[i])));
                h0[i] = fmaf(kA.w, fmaxf(pa, 0.f), h0[i]);
                float pbv = fmaf(A0[i], kB.x, fmaf(A1[i], kB.y,
                             fmaf(A2[i], kB.z, t1[i])));
                h1v[i] = fmaf(kB.w, fmaxf(pbv, 0.f), h1v[i]);
            }
        }
        #pragma unroll
        for (int i = 0; i < 8; i++) {
            const int c = lane + 32 * i;
            S.u.hb[c][0] = h0[i];
            S.u.hb[c][1] = h1v[i];
        }
    }
    __syncwarp();

    const int o1 = 2 * lane;

    // ---- layer 2: 256 -> 64, FFMA2, split even/odd chains ------------------
    unsigned long long aXe = 0, aXo = 0, aYe = 0, aYo = 0;
    {
        const float* wrow = g_wt2b + o1;
        #pragma unroll 4
        for (int c = 0; c < HH; c += 2) {
            const unsigned long long hE =
                *(const unsigned long long*)&S.u.hb[c][0];
            const unsigned long long hO =
                *(const unsigned long long*)&S.u.hb[c + 1][0];
            const float2 wE = *(const float2*)(wrow + c * CC);
            const float2 wO = *(const float2*)(wrow + (c + 1) * CC);
            unsigned long long w;
            DUP2(w, wE.x); FMA2(aXe, w, hE);
            DUP2(w, wE.y); FMA2(aYe, w, hE);
            DUP2(w, wO.x); FMA2(aXo, w, hO);
            DUP2(w, wO.y); FMA2(aYo, w, hO);
        }
    }
    ADD2(aXe, aXo); ADD2(aYe, aYo);
    float pfx[2], pfy[2];
    UNPK2(pfx[0], pfx[1], aXe);
    UNPK2(pfy[0], pfy[1], aYe);
    {
        const float2 bb2 = *(const float2*)(b2b + o1);
        #pragma unroll
        for (int p = 0; p < 2; p++) {
            pfx[p] = fmaf(bb2.x, ssum[p], pfx[p]);
            pfy[p] = fmaf(bb2.y, ssum[p], pfy[p]);
        }
    }

    // ---- close_feat + co_feature -------------------------------------------
    float cf0[2], cf1[2], co0[2], co1[2];
    #pragma unroll
    for (int p = 0; p < 2; p++) {
        const float2 f =
            *(const float2*)(feature + ((size_t)b * MM + ci[p]) * CC + o1);
        cf0[p] = f.x; cf1[p] = f.y; co0[p] = 0.f; co1[p] = 0.f;
    }
    for (int k = 0; k < KK; k++) {
        #pragma unroll
        for (int p = 0; p < 2; p++) {
            const float2 jw = *(const float2*)&S.jw[p][k][0];
            const int j = __float_as_int(jw.x);
            const float2 f =
                *(const float2*)(feature + ((size_t)b * MM + j) * CC + o1);
            co0[p] = fmaf(jw.y, f.x, co0[p]);
            co1[p] = fmaf(jw.y, f.y, co1[p]);
        }
    }
    __syncwarp();   // all lanes done reading hb before df overwrites it

    *(float2*)&S.u.s.df[o1][0]          = make_float2(cf0[0], cf0[1]);
    *(float2*)&S.u.s.df[o1 + 1][0]      = make_float2(cf1[0], cf1[1]);
    *(float2*)&S.u.s.df[CC + o1][0]     = make_float2(co0[0], co0[1]);
    *(float2*)&S.u.s.df[CC + o1 + 1][0] = make_float2(co1[0], co1[1]);
    *(float2*)&S.u.s.df[2 * CC + o1][0]     = make_float2(pfx[0], pfx[1]);
    *(float2*)&S.u.s.df[2 * CC + o1 + 1][0] = make_float2(pfy[0], pfy[1]);
    __syncwarp();

    // ---- final MLP layer 1: 192 -> 64, BN folded + ReLU --------------------
    unsigned long long fXe = 0, fXo = 0, fYe = 0, fYo = 0;
    {
        const float* wrow = g_wt1a + o1;
        #pragma unroll 4
        for (int c = 0; c < 3 * CC; c += 2) {
            const unsigned long long dE =
                *(const unsigned long long*)&S.u.s.df[c][0];
            const unsigned long long dO =
                *(const unsigned long long*)&S.u.s.df[c + 1][0];
            const float2 wE = *(const float2*)(wrow + c * CC);
            const float2 wO = *(const float2*)(wrow + (c + 1) * CC);
            unsigned long long w;
            DUP2(w, wE.x); FMA2(fXe, w, dE);
            DUP2(w, wE.y); FMA2(fYe, w, dE);
            DUP2(w, wO.x); FMA2(fXo, w, dO);
            DUP2(w, wO.y); FMA2(fYo, w, dO);
        }
    }
    ADD2(fXe, fXo); ADD2(fYe, fYo);
    {
        float ax[2], ay[2];
        UNPK2(ax[0], ax[1], fXe);
        UNPK2(ay[0], ay[1], fYe);
        const float2 s2 = *(const float2*)(g_f1s + o1);
        const float2 b2 = *(const float2*)(g_f1b + o1);
        float hx[2], hy[2];
        #pragma unroll
        for (int p = 0; p < 2; p++) {
            hx[p] = fmaxf(fmaf(ax[p], s2.x, b2.x), 0.f);
            hy[p] = fmaxf(fmaf(ay[p], s2.y, b2.y), 0.f);
        }
        *(float2*)&S.u.s.h1[o1][0]     = make_float2(hx[0], hx[1]);
        *(float2*)&S.u.s.h1[o1 + 1][0] = make_float2(hy[0], hy[1]);
    }
    __syncwarp();

    // ---- final MLP layer 2: 64 -> 64 ---------------------------------------
    unsigned long long rXe = 0, rXo = 0, rYe = 0, rYo = 0;
    {
        const float* wrow = g_wt1b + o1;
        #pragma unroll 4
        for (int c = 0; c < CC; c += 2) {
            const unsigned long long hE =
                *(const unsigned long long*)&S.u.s.h1[c][0];
            const unsigned long long hO =
                *(const unsigned long long*)&S.u.s.h1[c + 1][0];
            const float2 wE = *(const float2*)(wrow + c * CC);
            const float2 wO = *(const float2*)(wrow + (c + 1) * CC);
            unsigned long long w;
            DUP2(w, wE.x); FMA2(rXe, w, hE);
            DUP2(w, wE.y); FMA2(rYe, w, hE);
            DUP2(w, wO.x); FMA2(rXo, w, hO);
            DUP2(w, wO.y); FMA2(rYo, w, hO);
        }
    }
    ADD2(rXe, rXo); ADD2(rYe, rYo);
    {
        float rx[2], ry[2];
        UNPK2(rx[0], rx[1], rXe);
        UNPK2(ry[0], ry[1], rYe);
        const float2 bo = *(const float2*)(b1b + o1);
        #pragma unroll
        for (int p = 0; p < 2; p++) {
            *(float2*)(out + ((size_t)b * NN + n0 + p) * CC + o1) =
                make_float2(rx[p] + bo.x, ry[p] + bo.y);
        }
    }
}

// ---------------------------------------------------------------------------
extern "C" void kernel_launch(void* const* d_in, const int* in_sizes, int n_in,
                              void* d_out, int out_size)
{
    (void)in_sizes; (void)n_in; (void)out_size;
    const float* pcl       = (const float*)d_in[0];
    const float* pcl_noise = (const float*)d_in[1];
    const float* feature   = (const float*)d_in[2];
    const float* w2a  = (const float*)d_in[3];
    const float* b2a  = (const float*)d_in[4];
    const float* g2a  = (const float*)d_in[5];
    const float* bt2a = (const float*)d_in[6];
    const float* w2b  = (const float*)d_in[7];
    const float* b2b  = (const float*)d_in[8];
    const float* w1a  = (const float*)d_in[9];
    const float* b1a  = (const float*)d_in[10];
    const float* g1a  = (const float*)d_in[11];
    const float* bt1a = (const float*)d_in[12];
    const float* w1b  = (const float*)d_in[13];
    const float* b1b  = (const float*)d_in[14];
    float* out = (float*)d_out;

    prep_kernel<<<64, 256>>>(w2a, b2a, g2a, bt2a, w2b, w1a, b1a, g1a, bt1a, w1b);
    nn_part_kernel<<<dim3(NN / 128, NCHUNK, BB), 128>>>(pcl, pcl_noise);
    knn_kernel<<<dim3(MM / 16, BB), 512>>>(pcl);
    fused_kernel<<<(BB * NN) / 8, 128>>>(
        pcl, pcl_noise, feature, b2b, b1b, out);
}

// round 8
// speedup vs baseline: 7.3337x; 1.1051x over previous
#include <cuda_runtime.h>
#include <math.h>

#define BB  2
#define NN  8192
#define MM  4096
#define CC  64
#define KK  15      // K-1 neighbors actually used
#define HH  256
#define NCHUNK 8
#define CHM (MM / NCHUNK)   // 512

// Scratch (allocation-free rule: __device__ globals)
__device__ unsigned long long g_nn_part[BB * NCHUNK * NN];
__device__ int   g_knn[BB * MM * KK];
// prepped weights
__device__ float g_l1A[HH * 4];          // [c][{A0,A1,A2,B}]  (BN-folded)
__device__ float g_l1T[HH * 4];          // [c][{A3,A4,A5,0}]  (BN-folded)
__device__ float g_wt2b[HH * CC];        // [c][o]
__device__ float g_wt1a[3 * CC * CC];    // [c][o]
__device__ float g_wt1b[CC * CC];        // [c][o]
__device__ float g_f1s[CC];              // g1a*invs
__device__ float g_f1b[CC];              // b1a*g' + bt1a

#define FMA2(acc, a, b) \
    asm("fma.rn.f32x2 %0, %1, %2, %0;" : "+l"(acc) : "l"(a), "l"(b))
#define ADD2(acc, a) \
    asm("add.rn.f32x2 %0, %0, %1;" : "+l"(acc) : "l"(a))
#define UNPK2(lo, hi, v) \
    asm("mov.b64 {%0, %1}, %2;" : "=f"(lo), "=f"(hi) : "l"(v))
#define DUP2(out, v) \
    asm("mov.b64 %0, {%1, %1};" : "=l"(out) : "f"(v))

static __device__ __forceinline__ unsigned long long packkey(float d, int idx) {
    return ((unsigned long long)__float_as_uint(d) << 32) | (unsigned)idx;
}

// ---------------------------------------------------------------------------
// Kernel P: fold BN + transpose weight prep.
// ---------------------------------------------------------------------------
__global__ __launch_bounds__(256) void prep_kernel(
    const float* __restrict__ w2a, const float* __restrict__ b2a,
    const float* __restrict__ g2a, const float* __restrict__ bt2a,
    const float* __restrict__ w2b,
    const float* __restrict__ w1a, const float* __restrict__ b1a,
    const float* __restrict__ g1a, const float* __restrict__ bt1a,
    const float* __restrict__ w1b)
{
    const float invs = rsqrtf(1.0f + 1e-5f);
    const int t = blockIdx.x * 256 + threadIdx.x;
    const int stride = gridDim.x * 256;

    for (int c = t; c < HH; c += stride) {
        const float gp = g2a[c] * invs;
        g_l1A[c * 4 + 0] = w2a[c * 6 + 0] * gp;
        g_l1A[c * 4 + 1] = w2a[c * 6 + 1] * gp;
        g_l1A[c * 4 + 2] = w2a[c * 6 + 2] * gp;
        g_l1A[c * 4 + 3] = b2a[c] * gp + bt2a[c];
        g_l1T[c * 4 + 0] = w2a[c * 6 + 3] * gp;
        g_l1T[c * 4 + 1] = w2a[c * 6 + 4] * gp;
        g_l1T[c * 4 + 2] = w2a[c * 6 + 5] * gp;
        g_l1T[c * 4 + 3] = 0.f;
    }
    for (int idx = t; idx < HH * CC; idx += stride) {
        int c = idx / CC, o = idx - c * CC;
        g_wt2b[idx] = w2b[o * HH + c];
    }
    for (int idx = t; idx < 3 * CC * CC; idx += stride) {
        int c = idx / CC, o = idx - c * CC;
        g_wt1a[idx] = w1a[o * (3 * CC) + c];
    }
    for (int idx = t; idx < CC * CC; idx += stride) {
        int c = idx / CC, o = idx - c * CC;
        g_wt1b[idx] = w1b[o * CC + c];
    }
    for (int o = t; o < CC; o += stride) {
        const float s = g1a[o] * invs;
        g_f1s[o] = s;
        g_f1b[o] = b1a[o] * s + bt1a[o];
    }
}

// ---------------------------------------------------------------------------
// Kernel A: partial argmin over a 512-candidate chunk of pcl, per noisy pt.
// ---------------------------------------------------------------------------
__global__ __launch_bounds__(128) void nn_part_kernel(
    const float* __restrict__ pcl, const float* __restrict__ pcl_noise)
{
    const int b = blockIdx.z;
    const int chunk = blockIdx.y;
    const int n = blockIdx.x * 128 + threadIdx.x;
    const float* pb = pcl + (size_t)b * MM * 3 + (size_t)chunk * CHM * 3;

    const float qx = pcl_noise[((size_t)b * NN + n) * 3 + 0];
    const float qy = pcl_noise[((size_t)b * NN + n) * 3 + 1];
    const float qz = pcl_noise[((size_t)b * NN + n) * 3 + 2];

    __shared__ float sp[3 * CHM];
    for (int i = threadIdx.x; i < (3 * CHM) / 4; i += 128)
        ((float4*)sp)[i] = ((const float4*)pb)[i];
    __syncthreads();

    float best = 3.4e38f;
    int   bi   = 0;

    const float4* sp4 = (const float4*)sp;
    #pragma unroll 4
    for (int j = 0; j < CHM; j += 4) {
        const int f4 = (j * 3) >> 2;
        float4 a = sp4[f4], c1 = sp4[f4 + 1], c2 = sp4[f4 + 2];
        float dx, dy, dz;
        dx = a.x - qx;  dy = a.y - qy;  dz = a.z - qz;
        float d0 = dx * dx + dy * dy + dz * dz;
        dx = a.w - qx;  dy = c1.x - qy; dz = c1.y - qz;
        float d1 = dx * dx + dy * dy + dz * dz;
        dx = c1.z - qx; dy = c1.w - qy; dz = c2.x - qz;
        float d2 = dx * dx + dy * dy + dz * dz;
        dx = c2.y - qx; dy = c2.z - qy; dz = c2.w - qz;
        float d3 = dx * dx + dy * dy + dz * dz;

        if (d0 < best) { best = d0; bi = j;     }
        if (d1 < best) { best = d1; bi = j + 1; }
        if (d2 < best) { best = d2; bi = j + 2; }
        if (d3 < best) { best = d3; bi = j + 3; }
    }
    g_nn_part[((size_t)b * NCHUNK + chunk) * NN + n] =
        packkey(best, chunk * CHM + bi);
}

// ---------------------------------------------------------------------------
// Kernel B: self-KNN, one warp per query, 512-thread blocks, scan unrolled 2x.
// Distributed sorted top-16 in lanes 0..15 (u64 keys).
// ---------------------------------------------------------------------------
__global__ __launch_bounds__(512) void knn_kernel(const float* __restrict__ pcl)
{
    const int b = blockIdx.y;
    const int wrp  = threadIdx.x >> 5;
    const int lane = threadIdx.x & 31;
    const float* pb = pcl + (size_t)b * MM * 3;
    const unsigned FULL = 0xffffffffu;

    __shared__ float sx[MM], sy[MM], sz[MM];
    for (int i = threadIdx.x; i < 3 * MM; i += 512) {
        float v = pb[i];
        int m = i / 3, c = i - 3 * m;
        if (c == 0) sx[m] = v; else if (c == 1) sy[m] = v; else sz[m] = v;
    }
    __syncthreads();

    const int m = blockIdx.x * 16 + wrp;
    const float qx = sx[m], qy = sy[m], qz = sz[m];

    unsigned long long key = 0xffffffffffffffffull;   // lanes 0..15 = list
    unsigned long long kmk = 0xffffffffffffffffull;
    float kmd = 3.4e38f;

    for (int t = 0; t < MM / 32; t += 2) {
        const int j0 = lane + 32 * t;
        const int j1 = j0 + 32;
        const float dx0 = sx[j0] - qx, dy0 = sy[j0] - qy, dz0 = sz[j0] - qz;
        const float dx1 = sx[j1] - qx, dy1 = sy[j1] - qy, dz1 = sz[j1] - qz;
        const float dc0 = fmaf(dx0, dx0, fmaf(dy0, dy0, dz0 * dz0));
        const float dc1 = fmaf(dx1, dx1, fmaf(dy1, dy1, dz1 * dz1));

        #pragma unroll
        for (int u = 0; u < 2; u++) {
            const float dc = u ? dc1 : dc0;
            const int jb = 32 * t + (u ? 32 : 0);
            unsigned pend = __ballot_sync(FULL, dc <= kmd);
            while (pend) {
                const int src = __ffs(pend) - 1;
                pend &= pend - 1;
                const float dcc = __shfl_sync(FULL, dc, src);
                const unsigned long long kc = packkey(dcc, src + jb);
                if (kc < kmk) {
                    const unsigned bal =
                        __ballot_sync(FULL, key > kc) & 0xFFFFu;
                    const int p = __ffs(bal) - 1;
                    const unsigned long long up = __shfl_up_sync(FULL, key, 1);
                    if (lane == p)      key = kc;
                    else if (lane > p)  key = up;
                    kmk = __shfl_sync(FULL, key, 15);
                    kmd = __uint_as_float((unsigned)(kmk >> 32));
                }
            }
        }
    }

    // rank 0 is the self point; emit ranks 1..15
    const int base = (b * MM + m) * KK;
    if (lane >= 1 && lane <= KK)
        g_knn[base + lane - 1] = (int)(key & 0xffffffffu);
}

// ---------------------------------------------------------------------------
// Kernel C: fused NN-merge + gather + MLPs. One warp per 4 POINTS with
// non-duplicated [c][o] weights ({v,v}-packed at use) -> 33KB weight-L1
// traffic per point (half of the 2pt version). Activation LDS.128 serves
// all 4 points. Even/odd split accumulator chains. Unioned smem phases.
// ---------------------------------------------------------------------------
struct __align__(16) WarpSm {
    float kd[4][16][4];   // [p][k][dx,dy,dz,lw]
    float jw[4][16][2];   // [p][k][jk(bits), lw]
    union {
        float hb[HH][4];              // 4096 B, phase 1-2
        struct {
            float df[3 * CC][4];      // 3072 B, phase 3
            float h1[CC][4];          // 1024 B, phase 4
        } s;
    } u;
};

__global__ __launch_bounds__(128) void fused_kernel(
    const float* __restrict__ pcl,  const float* __restrict__ pcl_noise,
    const float* __restrict__ feature,
    const float* __restrict__ b2b,  const float* __restrict__ b1b,
    float* __restrict__ out)
{
    const int wrp  = threadIdx.x >> 5;
    const int lane = threadIdx.x & 31;
    const int pt0  = (blockIdx.x * 4 + wrp) * 4;   // 4 consecutive points
    const int b    = pt0 >> 13;
    const int n0   = pt0 & (NN - 1);
    const unsigned FULL = 0xffffffffu;

    __shared__ WarpSm sm[4];
    WarpSm& S = sm[wrp];

    // ---- distributed NN-merge: lane = p*8 + chunk --------------------------
    int ci[4];
    {
        const int p = lane >> 3, c = lane & 7;
        unsigned long long k =
            g_nn_part[((size_t)b * NCHUNK + c) * NN + (n0 + p)];
        unsigned long long o;
        o = __shfl_xor_sync(FULL, k, 4); if (o < k) k = o;
        o = __shfl_xor_sync(FULL, k, 2); if (o < k) k = o;
        o = __shfl_xor_sync(FULL, k, 1); if (o < k) k = o;
        #pragma unroll
        for (int p2 = 0; p2 < 4; p2++)
            ci[p2] = (int)(__shfl_sync(FULL, k, p2 * 8) & 0xffffffffu);
    }

    // ---- query coords (3x LDG.128 broadcast) + close points ----------------
    float qx[4], qy[4], qz[4], cpx[4], cpy[4], cpz[4];
    {
        const float4* q4 =
            (const float4*)(pcl_noise + ((size_t)b * NN + n0) * 3);
        const float4 Q0 = q4[0], Q1 = q4[1], Q2 = q4[2];
        qx[0] = Q0.x; qy[0] = Q0.y; qz[0] = Q0.z;
        qx[1] = Q0.w; qy[1] = Q1.x; qz[1] = Q1.y;
        qx[2] = Q1.z; qy[2] = Q1.w; qz[2] = Q2.x;
        qx[3] = Q2.y; qy[3] = Q2.z; qz[3] = Q2.w;
        #pragma unroll
        for (int p = 0; p < 4; p++) {
            const float* cp = pcl + ((size_t)b * MM + ci[p]) * 3;
            cpx[p] = cp[0]; cpy[p] = cp[1]; cpz[p] = cp[2];
        }
    }

    // ---- neighbors: lane k owns neighbor k of each point -------------------
    float ssum[4];
    #pragma unroll
    for (int p = 0; p < 4; p++) {
        int jk = 0; float dx = 0.f, dy = 0.f, dz = 0.f, e = 0.f;
        if (lane < KK) {
            jk = g_knn[(b * MM + ci[p]) * KK + lane];
            const float* pp = pcl + ((size_t)b * MM + jk) * 3;
            dx = pp[0] - qx[p]; dy = pp[1] - qy[p]; dz = pp[2] - qz[p];
            e = expf(-10.0f * sqrtf(dx * dx + dy * dy + dz * dz));
        }
        float Sv = e;
        #pragma unroll
        for (int o = 16; o; o >>= 1) Sv += __shfl_xor_sync(FULL, Sv, o);
        const float lw = e / (Sv + 1e-7f);
        ssum[p] = Sv / (Sv + 1e-7f);
        if (lane < KK) {
            *(float4*)&S.kd[p][lane][0] = make_float4(dx, dy, dz, lw);
            *(float2*)&S.jw[p][lane][0] =
                make_float2(__int_as_float(jk), lw);
        }
    }
    __syncwarp();

    // ---- layer 1 (6 -> 256, BN folded), 2 passes of 2 points ---------------
    #pragma unroll
    for (int s = 0; s < 2; s++) {
        const int p0 = 2 * s, p1 = 2 * s + 1;
        float A0[8], A1[8], A2[8], t0[8], t1[8], h0[8], h1v[8];
        #pragma unroll
        for (int i = 0; i < 8; i++) {
            const int c = lane + 32 * i;
            const float4 wA = *(const float4*)&g_l1A[c * 4];
            const float4 wT = *(const float4*)&g_l1T[c * 4];
            A0[i] = wA.x; A1[i] = wA.y; A2[i] = wA.z;
            t0[i] = fmaf(wT.x, cpx[p0], fmaf(wT.y, cpy[p0],
                     fmaf(wT.z, cpz[p0], wA.w)));
            t1[i] = fmaf(wT.x, cpx[p1], fmaf(wT.y, cpy[p1],
                     fmaf(wT.z, cpz[p1], wA.w)));
            h0[i] = 0.f; h1v[i] = 0.f;
        }
        for (int k = 0; k < KK; k++) {
            const float4 kA = *(const float4*)&S.kd[p0][k][0];
            const float4 kB = *(const float4*)&S.kd[p1][k][0];
            #pragma unroll
            for (int i = 0; i < 8; i++) {
                float pa = fmaf(A0[i], kA.x, fmaf(A1[i], kA.y,
                            fmaf(A2[i], kA.z, t0[i])));
                h0[i] = fmaf(kA.w, fmaxf(pa, 0.f), h0[i]);
                float pbv = fmaf(A0[i], kB.x, fmaf(A1[i], kB.y,
                             fmaf(A2[i], kB.z, t1[i])));
                h1v[i] = fmaf(kB.w, fmaxf(pbv, 0.f), h1v[i]);
            }
        }
        #pragma unroll
        for (int i = 0; i < 8; i++) {
            const int c = lane + 32 * i;
            S.u.hb[c][p0] = h0[i];
            S.u.hb[c][p1] = h1v[i];
        }
    }
    __syncwarp();

    const int o1 = 2 * lane;

    // ---- layer 2: 256 -> 64, FFMA2, split even/odd chains ------------------
    unsigned long long aXe0 = 0, aXe1 = 0, aXo0 = 0, aXo1 = 0;
    unsigned long long aYe0 = 0, aYe1 = 0, aYo0 = 0, aYo1 = 0;
    {
        const float* wrow = g_wt2b + o1;
        #pragma unroll 4
        for (int c = 0; c < HH; c += 2) {
            const ulonglong2 hE = *(const ulonglong2*)&S.u.hb[c][0];
            const ulonglong2 hO = *(const ulonglong2*)&S.u.hb[c + 1][0];
            const float2 wE = *(const float2*)(wrow + c * CC);
            const float2 wO = *(const float2*)(wrow + (c + 1) * CC);
            unsigned long long w;
            DUP2(w, wE.x); FMA2(aXe0, w, hE.x); FMA2(aXe1, w, hE.y);
            DUP2(w, wE.y); FMA2(aYe0, w, hE.x); FMA2(aYe1, w, hE.y);
            DUP2(w, wO.x); FMA2(aXo0, w, hO.x); FMA2(aXo1, w, hO.y);
            DUP2(w, wO.y); FMA2(aYo0, w, hO.x); FMA2(aYo1, w, hO.y);
        }
    }
    ADD2(aXe0, aXo0); ADD2(aXe1, aXo1);
    ADD2(aYe0, aYo0); ADD2(aYe1, aYo1);
    float pfx[4], pfy[4];
    UNPK2(pfx[0], pfx[1], aXe0); UNPK2(pfx[2], pfx[3], aXe1);
    UNPK2(pfy[0], pfy[1], aYe0); UNPK2(pfy[2], pfy[3], aYe1);
    {
        const float2 bb2 = *(const float2*)(b2b + o1);
        #pragma unroll
        for (int p = 0; p < 4; p++) {
            pfx[p] = fmaf(bb2.x, ssum[p], pfx[p]);
            pfy[p] = fmaf(bb2.y, ssum[p], pfy[p]);
        }
    }

    // ---- close_feat + co_feature -------------------------------------------
    float cf0[4], cf1[4], co0[4], co1[4];
    #pragma unroll
    for (int p = 0; p < 4; p++) {
        const float2 f =
            *(const float2*)(feature + ((size_t)b * MM + ci[p]) * CC + o1);
        cf0[p] = f.x; cf1[p] = f.y; co0[p] = 0.f; co1[p] = 0.f;
    }
    for (int k = 0; k < KK; k++) {
        #pragma unroll
        for (int p = 0; p < 4; p++) {
            const float2 jw = *(const float2*)&S.jw[p][k][0];
            const int j = __float_as_int(jw.x);
            const float2 f =
                *(const float2*)(feature + ((size_t)b * MM + j) * CC + o1);
            co0[p] = fmaf(jw.y, f.x, co0[p]);
            co1[p] = fmaf(jw.y, f.y, co1[p]);
        }
    }
    __syncwarp();   // all lanes done reading hb before df overwrites it

    *(float4*)&S.u.s.df[o1][0]          = make_float4(cf0[0], cf0[1], cf0[2], cf0[3]);
    *(float4*)&S.u.s.df[o1 + 1][0]      = make_float4(cf1[0], cf1[1], cf1[2], cf1[3]);
    *(float4*)&S.u.s.df[CC + o1][0]     = make_float4(co0[0], co0[1], co0[2], co0[3]);
    *(float4*)&S.u.s.df[CC + o1 + 1][0] = make_float4(co1[0], co1[1], co1[2], co1[3]);
    *(float4*)&S.u.s.df[2 * CC + o1][0]     = make_float4(pfx[0], pfx[1], pfx[2], pfx[3]);
    *(float4*)&S.u.s.df[2 * CC + o1 + 1][0] = make_float4(pfy[0], pfy[1], pfy[2], pfy[3]);
    __syncwarp();

    // ---- final MLP layer 1: 192 -> 64, BN folded + ReLU --------------------
    unsigned long long fXe0 = 0, fXe1 = 0, fXo0 = 0, fXo1 = 0;
    unsigned long long fYe0 = 0, fYe1 = 0, fYo0 = 0, fYo1 = 0;
    {
        const float* wrow = g_wt1a + o1;
        #pragma unroll 4
        for (int c = 0; c < 3 * CC; c += 2) {
            const ulonglong2 dE = *(const ulonglong2*)&S.u.s.df[c][0];
            const ulonglong2 dO = *(const ulonglong2*)&S.u.s.df[c + 1][0];
            const float2 wE = *(const float2*)(wrow + c * CC);
            const float2 wO = *(const float2*)(wrow + (c + 1) * CC);
            unsigned long long w;
            DUP2(w, wE.x); FMA2(fXe0, w, dE.x); FMA2(fXe1, w, dE.y);
            DUP2(w, wE.y); FMA2(fYe0, w, dE.x); FMA2(fYe1, w, dE.y);
            DUP2(w, wO.x); FMA2(fXo0, w, dO.x); FMA2(fXo1, w, dO.y);
            DUP2(w, wO.y); FMA2(fYo0, w, dO.x); FMA2(fYo1, w, dO.y);
        }
    }
    ADD2(fXe0, fXo0); ADD2(fXe1, fXo1);
    ADD2(fYe0, fYo0); ADD2(fYe1, fYo1);
    {
        float ax[4], ay[4];
        UNPK2(ax[0], ax[1], fXe0); UNPK2(ax[2], ax[3], fXe1);
        UNPK2(ay[0], ay[1], fYe0); UNPK2(ay[2], ay[3], fYe1);
        const float2 s2 = *(const float2*)(g_f1s + o1);
        const float2 b2 = *(const float2*)(g_f1b + o1);
        float hx[4], hy[4];
        #pragma unroll
        for (int p = 0; p < 4; p++) {
            hx[p] = fmaxf(fmaf(ax[p], s2.x, b2.x), 0.f);
            hy[p] = fmaxf(fmaf(ay[p], s2.y, b2.y), 0.f);
        }
        *(float4*)&S.u.s.h1[o1][0]     = make_float4(hx[0], hx[1], hx[2], hx[3]);
        *(float4*)&S.u.s.h1[o1 + 1][0] = make_float4(hy[0], hy[1], hy[2], hy[3]);
    }
    __syncwarp();

    // ---- final MLP layer 2: 64 -> 64 ---------------------------------------
    unsigned long long rXe0 = 0, rXe1 = 0, rXo0 = 0, rXo1 = 0;
    unsigned long long rYe0 = 0, rYe1 = 0, rYo0 = 0, rYo1 = 0;
    {
        const float* wrow = g_wt1b + o1;
        #pragma unroll 4
        for (int c = 0; c < CC; c += 2) {
            const ulonglong2 hE = *(const ulonglong2*)&S.u.s.h1[c][0];
            const ulonglong2 hO = *(const ulonglong2*)&S.u.s.h1[c + 1][0];
            const float2 wE = *(const float2*)(wrow + c * CC);
            const float2 wO = *(const float2*)(wrow + (c + 1) * CC);
            unsigned long long w;
            DUP2(w, wE.x); FMA2(rXe0, w, hE.x); FMA2(rXe1, w, hE.y);
            DUP2(w, wE.y); FMA2(rYe0, w, hE.x); FMA2(rYe1, w, hE.y);
            DUP2(w, wO.x); FMA2(rXo0, w, hO.x); FMA2(rXo1, w, hO.y);
            DUP2(w, wO.y); FMA2(rYo0, w, hO.x); FMA2(rYo1, w, hO.y);
        }
    }
    ADD2(rXe0, rXo0); ADD2(rXe1, rXo1);
    ADD2(rYe0, rYo0); ADD2(rYe1, rYo1);
    {
        float rx[4], ry[4];
        UNPK2(rx[0], rx[1], rXe0); UNPK2(rx[2], rx[3], rXe1);
        UNPK2(ry[0], ry[1], rYe0); UNPK2(ry[2], ry[3], rYe1);
        const float2 bo = *(const float2*)(b1b + o1);
        #pragma unroll
        for (int p = 0; p < 4; p++) {
            *(float2*)(out + ((size_t)b * NN + n0 + p) * CC + o1) =
                make_float2(rx[p] + bo.x, ry[p] + bo.y);
        }
    }
}

// ---------------------------------------------------------------------------
extern "C" void kernel_launch(void* const* d_in, const int* in_sizes, int n_in,
                              void* d_out, int out_size)
{
    (void)in_sizes; (void)n_in; (void)out_size;
    const float* pcl       = (const float*)d_in[0];
    const float* pcl_noise = (const float*)d_in[1];
    const float* feature   = (const float*)d_in[2];
    const float* w2a  = (const float*)d_in[3];
    const float* b2a  = (const float*)d_in[4];
    const float* g2a  = (const float*)d_in[5];
    const float* bt2a = (const float*)d_in[6];
    const float* w2b  = (const float*)d_in[7];
    const float* b2b  = (const float*)d_in[8];
    const float* w1a  = (const float*)d_in[9];
    const float* b1a  = (const float*)d_in[10];
    const float* g1a  = (const float*)d_in[11];
    const float* bt1a = (const float*)d_in[12];
    const float* w1b  = (const float*)d_in[13];
    const float* b1b  = (const float*)d_in[14];
    float* out = (float*)d_out;

    prep_kernel<<<64, 256>>>(w2a, b2a, g2a, bt2a, w2b, w1a, b1a, g1a, bt1a, w1b);
    nn_part_kernel<<<dim3(NN / 128, NCHUNK, BB), 128>>>(pcl, pcl_noise);
    knn_kernel<<<dim3(MM / 16, BB), 512>>>(pcl);
    fused_kernel<<<(BB * NN) / 16, 128>>>(
        pcl, pcl_noise, feature, b2b, b1b, out);
}

// round 10
// speedup vs baseline: 7.8759x; 1.0739x over previous
#include <cuda_runtime.h>
#include <math.h>

#define BB  2
#define NN  8192
#define MM  4096
#define CC  64
#define KK  15      // K-1 neighbors actually used
#define HH  256
#define NCHUNK 8
#define CHM (MM / NCHUNK)   // 512

// Scratch (allocation-free rule: __device__ globals)
__device__ unsigned long long g_nn_part[BB * NCHUNK * NN];
__device__ int   g_knn[BB * MM * KK];
// prepped weights
__device__ float g_l1A[HH * 4];          // [c][{A0,A1,A2,B}]  (BN-folded)
__device__ float g_l1T[HH * 4];          // [c][{A3,A4,A5,0}]  (BN-folded)
__device__ float g_wt2b[HH * CC];        // [c][o]
__device__ float g_wt1a[3 * CC * CC];    // [c][o]
__device__ float g_wt1b[CC * CC];        // [c][o]
__device__ float g_f1s[CC];              // g1a*invs
__device__ float g_f1b[CC];              // b1a*g' + bt1a

#define FMA2(acc, a, b) \
    asm("fma.rn.f32x2 %0, %1, %2, %0;" : "+l"(acc) : "l"(a), "l"(b))
#define ADD2(acc, a) \
    asm("add.rn.f32x2 %0, %0, %1;" : "+l"(acc) : "l"(a))
#define UNPK2(lo, hi, v) \
    asm("mov.b64 {%0, %1}, %2;" : "=f"(lo), "=f"(hi) : "l"(v))
#define DUP2(out, v) \
    asm("mov.b64 %0, {%1, %1};" : "=l"(out) : "f"(v))

static __device__ __forceinline__ unsigned long long packkey(float d, int idx) {
    return ((unsigned long long)__float_as_uint(d) << 32) | (unsigned)idx;
}

// ---------------------------------------------------------------------------
// Kernel P: fold BN + transpose weight prep.
// ---------------------------------------------------------------------------
__global__ __launch_bounds__(256) void prep_kernel(
    const float* __restrict__ w2a, const float* __restrict__ b2a,
    const float* __restrict__ g2a, const float* __restrict__ bt2a,
    const float* __restrict__ w2b,
    const float* __restrict__ w1a, const float* __restrict__ b1a,
    const float* __restrict__ g1a, const float* __restrict__ bt1a,
    const float* __restrict__ w1b)
{
    const float invs = rsqrtf(1.0f + 1e-5f);
    const int t = blockIdx.x * 256 + threadIdx.x;
    const int stride = gridDim.x * 256;

    for (int c = t; c < HH; c += stride) {
        const float gp = g2a[c] * invs;
        g_l1A[c * 4 + 0] = w2a[c * 6 + 0] * gp;
        g_l1A[c * 4 + 1] = w2a[c * 6 + 1] * gp;
        g_l1A[c * 4 + 2] = w2a[c * 6 + 2] * gp;
        g_l1A[c * 4 + 3] = b2a[c] * gp + bt2a[c];
        g_l1T[c * 4 + 0] = w2a[c * 6 + 3] * gp;
        g_l1T[c * 4 + 1] = w2a[c * 6 + 4] * gp;
        g_l1T[c * 4 + 2] = w2a[c * 6 + 5] * gp;
        g_l1T[c * 4 + 3] = 0.f;
    }
    for (int idx = t; idx < HH * CC; idx += stride) {
        int c = idx / CC, o = idx - c * CC;
        g_wt2b[idx] = w2b[o * HH + c];
    }
    for (int idx = t; idx < 3 * CC * CC; idx += stride) {
        int c = idx / CC, o = idx - c * CC;
        g_wt1a[idx] = w1a[o * (3 * CC) + c];
    }
    for (int idx = t; idx < CC * CC; idx += stride) {
        int c = idx / CC, o = idx - c * CC;
        g_wt1b[idx] = w1b[o * CC + c];
    }
    for (int o = t; o < CC; o += stride) {
        const float s = g1a[o] * invs;
        g_f1s[o] = s;
        g_f1b[o] = b1a[o] * s + bt1a[o];
    }
}

// ---------------------------------------------------------------------------
// Kernel A: partial argmin over a 512-candidate chunk. float4 smem tile
// (x,y,z,pad); EXACT difference-based distance (matches reference
// conditioning — the norm/dot trick flips neighbor selection).
// ---------------------------------------------------------------------------
__global__ __launch_bounds__(128) void nn_part_kernel(
    const float* __restrict__ pcl, const float* __restrict__ pcl_noise)
{
    const int b = blockIdx.z;
    const int chunk = blockIdx.y;
    const int n = blockIdx.x * 128 + threadIdx.x;
    const float* pb = pcl + (size_t)b * MM * 3 + (size_t)chunk * CHM * 3;

    const float qx = pcl_noise[((size_t)b * NN + n) * 3 + 0];
    const float qy = pcl_noise[((size_t)b * NN + n) * 3 + 1];
    const float qz = pcl_noise[((size_t)b * NN + n) * 3 + 2];

    __shared__ float4 sp[CHM];
    for (int m = threadIdx.x; m < CHM; m += 128)
        sp[m] = make_float4(pb[3 * m], pb[3 * m + 1], pb[3 * m + 2], 0.f);
    __syncthreads();

    float best = 3.4e38f;
    int   bi   = 0;

    #pragma unroll 8
    for (int j = 0; j < CHM; j++) {
        const float4 p = sp[j];
        const float dx = p.x - qx, dy = p.y - qy, dz = p.z - qz;
        const float dc = fmaf(dx, dx, fmaf(dy, dy, dz * dz));
        if (dc < best) { best = dc; bi = j; }
    }
    g_nn_part[((size_t)b * NCHUNK + chunk) * NN + n] =
        packkey(best, chunk * CHM + bi);
}

// ---------------------------------------------------------------------------
// Kernel B: self-KNN, one warp per query, 1024-thread blocks, 64KB dynamic
// smem float4 tile (1 LDS.128 per candidate). Exact difference distances.
// Distributed sorted top-16 in lanes 0..15 (plain u64 keys, d >= 0).
// ---------------------------------------------------------------------------
__global__ __launch_bounds__(1024) void knn_kernel(const float* __restrict__ pcl)
{
    extern __shared__ float4 sp[];
    const int b = blockIdx.y;
    const int wrp  = threadIdx.x >> 5;
    const int lane = threadIdx.x & 31;
    const float* pb = pcl + (size_t)b * MM * 3;
    const unsigned FULL = 0xffffffffu;

    for (int m = threadIdx.x; m < MM; m += 1024)
        sp[m] = make_float4(pb[3 * m], pb[3 * m + 1], pb[3 * m + 2], 0.f);
    __syncthreads();

    const int m = blockIdx.x * 32 + wrp;
    const float4 q = sp[m];
    const float qx = q.x, qy = q.y, qz = q.z;

    unsigned long long key = 0xffffffffffffffffull;   // lanes 0..15 = list
    unsigned long long kmk = 0xffffffffffffffffull;
    float kmd = 3.4e38f;

    #pragma unroll 2
    for (int t = 0; t < MM / 32; t++) {
        const int j = lane + 32 * t;
        const float4 p = sp[j];
        const float dx = p.x - qx, dy = p.y - qy, dz = p.z - qz;
        const float dc = fmaf(dx, dx, fmaf(dy, dy, dz * dz));

        unsigned pend = __ballot_sync(FULL, dc <= kmd);
        while (pend) {
            const int src = __ffs(pend) - 1;
            pend &= pend - 1;
            const float dcc = __shfl_sync(FULL, dc, src);
            const unsigned long long kc = packkey(dcc, src + 32 * t);
            if (kc < kmk) {
                const unsigned bal = __ballot_sync(FULL, key > kc) & 0xFFFFu;
                const int p2 = __ffs(bal) - 1;
                const unsigned long long up = __shfl_up_sync(FULL, key, 1);
                if (lane == p2)      key = kc;
                else if (lane > p2)  key = up;
                kmk = __shfl_sync(FULL, key, 15);
                kmd = __uint_as_float((unsigned)(kmk >> 32));
            }
        }
    }

    // rank 0 is the self point; emit ranks 1..15
    const int base = (b * MM + m) * KK;
    if (lane >= 1 && lane <= KK)
        g_knn[base + lane - 1] = (int)(key & 0xffffffffu);
}

// ---------------------------------------------------------------------------
// Kernel C: fused NN-merge + gather + MLPs. One warp per 4 points.
// Layer 1 in 2 channel-half passes (lower reg pressure);
// __launch_bounds__(128,5) targets ~100 regs -> 20 warps/SM.
// ---------------------------------------------------------------------------
struct __align__(16) WarpSm {
    float kd[4][16][4];   // [p][k][dx,dy,dz,lw]
    float jw[4][16][2];   // [p][k][jk(bits), lw]
    union {
        float hb[HH][4];              // 4096 B, phase 1-2
        struct {
            float df[3 * CC][4];      // 3072 B, phase 3
            float h1[CC][4];          // 1024 B, phase 4
        } s;
    } u;
};

__global__ __launch_bounds__(128, 5) void fused_kernel(
    const float* __restrict__ pcl,  const float* __restrict__ pcl_noise,
    const float* __restrict__ feature,
    const float* __restrict__ b2b,  const float* __restrict__ b1b,
    float* __restrict__ out)
{
    const int wrp  = threadIdx.x >> 5;
    const int lane = threadIdx.x & 31;
    const int pt0  = (blockIdx.x * 4 + wrp) * 4;   // 4 consecutive points
    const int b    = pt0 >> 13;
    const int n0   = pt0 & (NN - 1);
    const unsigned FULL = 0xffffffffu;

    __shared__ WarpSm sm[4];
    WarpSm& S = sm[wrp];

    // ---- distributed NN-merge: lane = p*8 + chunk --------------------------
    int ci[4];
    {
        const int p = lane >> 3, c = lane & 7;
        unsigned long long k =
            g_nn_part[((size_t)b * NCHUNK + c) * NN + (n0 + p)];
        unsigned long long o;
        o = __shfl_xor_sync(FULL, k, 4); if (o < k) k = o;
        o = __shfl_xor_sync(FULL, k, 2); if (o < k) k = o;
        o = __shfl_xor_sync(FULL, k, 1); if (o < k) k = o;
        #pragma unroll
        for (int p2 = 0; p2 < 4; p2++)
            ci[p2] = (int)(__shfl_sync(FULL, k, p2 * 8) & 0xffffffffu);
    }

    // ---- query coords (3x LDG.128 broadcast) + close points ----------------
    float qx[4], qy[4], qz[4], cpx[4], cpy[4], cpz[4];
    {
        const float4* q4 =
            (const float4*)(pcl_noise + ((size_t)b * NN + n0) * 3);
        const float4 Q0 = q4[0], Q1 = q4[1], Q2 = q4[2];
        qx[0] = Q0.x; qy[0] = Q0.y; qz[0] = Q0.z;
        qx[1] = Q0.w; qy[1] = Q1.x; qz[1] = Q1.y;
        qx[2] = Q1.z; qy[2] = Q1.w; qz[2] = Q2.x;
        qx[3] = Q2.y; qy[3] = Q2.z; qz[3] = Q2.w;
        #pragma unroll
        for (int p = 0; p < 4; p++) {
            const float* cp = pcl + ((size_t)b * MM + ci[p]) * 3;
            cpx[p] = cp[0]; cpy[p] = cp[1]; cpz[p] = cp[2];
        }
    }

    // ---- neighbors: lane k owns neighbor k of each point -------------------
    float ssum[4];
    #pragma unroll
    for (int p = 0; p < 4; p++) {
        int jk = 0; float dx = 0.f, dy = 0.f, dz = 0.f, e = 0.f;
        if (lane < KK) {
            jk = g_knn[(b * MM + ci[p]) * KK + lane];
            const float* pp = pcl + ((size_t)b * MM + jk) * 3;
            dx = pp[0] - qx[p]; dy = pp[1] - qy[p]; dz = pp[2] - qz[p];
            e = expf(-10.0f * sqrtf(dx * dx + dy * dy + dz * dz));
        }
        float Sv = e;
        #pragma unroll
        for (int o = 16; o; o >>= 1) Sv += __shfl_xor_sync(FULL, Sv, o);
        const float lw = e / (Sv + 1e-7f);
        ssum[p] = Sv / (Sv + 1e-7f);
        if (lane < KK) {
            *(float4*)&S.kd[p][lane][0] = make_float4(dx, dy, dz, lw);
            *(float2*)&S.jw[p][lane][0] =
                make_float2(__int_as_float(jk), lw);
        }
    }
    __syncwarp();

    // ---- layer 1 (6 -> 256, BN folded): 2 passes of 4 channels x 4 points --
    #pragma unroll
    for (int s = 0; s < 2; s++) {
        float A0[4], A1[4], A2[4], t[4][4], h[4][4];
        #pragma unroll
        for (int i = 0; i < 4; i++) {
            const int c = lane + 32 * (4 * s + i);
            const float4 wA = *(const float4*)&g_l1A[c * 4];
            const float4 wT = *(const float4*)&g_l1T[c * 4];
            A0[i] = wA.x; A1[i] = wA.y; A2[i] = wA.z;
            #pragma unroll
            for (int p = 0; p < 4; p++) {
                t[i][p] = fmaf(wT.x, cpx[p], fmaf(wT.y, cpy[p],
                           fmaf(wT.z, cpz[p], wA.w)));
                h[i][p] = 0.f;
            }
        }
        for (int k = 0; k < KK; k++) {
            float4 kd[4];
            #pragma unroll
            for (int p = 0; p < 4; p++) kd[p] = *(const float4*)&S.kd[p][k][0];
            #pragma unroll
            for (int i = 0; i < 4; i++) {
                #pragma unroll
                for (int p = 0; p < 4; p++) {
                    const float pre = fmaf(A0[i], kd[p].x, fmaf(A1[i], kd[p].y,
                                       fmaf(A2[i], kd[p].z, t[i][p])));
                    h[i][p] = fmaf(kd[p].w, fmaxf(pre, 0.f), h[i][p]);
                }
            }
        }
        #pragma unroll
        for (int i = 0; i < 4; i++) {
            const int c = lane + 32 * (4 * s + i);
            *(float4*)&S.u.hb[c][0] =
                make_float4(h[i][0], h[i][1], h[i][2], h[i][3]);
        }
    }
    __syncwarp();

    const int o1 = 2 * lane;

    // ---- layer 2: 256 -> 64, FFMA2, split even/odd chains ------------------
    unsigned long long aXe0 = 0, aXe1 = 0, aXo0 = 0, aXo1 = 0;
    unsigned long long aYe0 = 0, aYe1 = 0, aYo0 = 0, aYo1 = 0;
    {
        const float* wrow = g_wt2b + o1;
        #pragma unroll 4
        for (int c = 0; c < HH; c += 2) {
            const ulonglong2 hE = *(const ulonglong2*)&S.u.hb[c][0];
            const ulonglong2 hO = *(const ulonglong2*)&S.u.hb[c + 1][0];
            const float2 wE = *(const float2*)(wrow + c * CC);
            const float2 wO = *(const float2*)(wrow + (c + 1) * CC);
            unsigned long long w;
            DUP2(w, wE.x); FMA2(aXe0, w, hE.x); FMA2(aXe1, w, hE.y);
            DUP2(w, wE.y); FMA2(aYe0, w, hE.x); FMA2(aYe1, w, hE.y);
            DUP2(w, wO.x); FMA2(aXo0, w, hO.x); FMA2(aXo1, w, hO.y);
            DUP2(w, wO.y); FMA2(aYo0, w, hO.x); FMA2(aYo1, w, hO.y);
        }
    }
    ADD2(aXe0, aXo0); ADD2(aXe1, aXo1);
    ADD2(aYe0, aYo0); ADD2(aYe1, aYo1);
    float pfx[4], pfy[4];
    UNPK2(pfx[0], pfx[1], aXe0); UNPK2(pfx[2], pfx[3], aXe1);
    UNPK2(pfy[0], pfy[1], aYe0); UNPK2(pfy[2], pfy[3], aYe1);
    {
        const float2 bb2 = *(const float2*)(b2b + o1);
        #pragma unroll
        for (int p = 0; p < 4; p++) {
            pfx[p] = fmaf(bb2.x, ssum[p], pfx[p]);
            pfy[p] = fmaf(bb2.y, ssum[p], pfy[p]);
        }
    }

    // ---- close_feat + co_feature -------------------------------------------
    float cf0[4], cf1[4], co0[4], co1[4];
    #pragma unroll
    for (int p = 0; p < 4; p++) {
        const float2 f =
            *(const float2*)(feature + ((size_t)b * MM + ci[p]) * CC + o1);
        cf0[p] = f.x; cf1[p] = f.y; co0[p] = 0.f; co1[p] = 0.f;
    }
    for (int k = 0; k < KK; k++) {
        #pragma unroll
        for (int p = 0; p < 4; p++) {
            const float2 jw = *(const float2*)&S.jw[p][k][0];
            const int j = __float_as_int(jw.x);
            const float2 f =
                *(const float2*)(feature + ((size_t)b * MM + j) * CC + o1);
            co0[p] = fmaf(jw.y, f.x, co0[p]);
            co1[p] = fmaf(jw.y, f.y, co1[p]);
        }
    }
    __syncwarp();   // all lanes done reading hb before df overwrites it

    *(float4*)&S.u.s.df[o1][0]          = make_float4(cf0[0], cf0[1], cf0[2], cf0[3]);
    *(float4*)&S.u.s.df[o1 + 1][0]      = make_float4(cf1[0], cf1[1], cf1[2], cf1[3]);
    *(float4*)&S.u.s.df[CC + o1][0]     = make_float4(co0[0], co0[1], co0[2], co0[3]);
    *(float4*)&S.u.s.df[CC + o1 + 1][0] = make_float4(co1[0], co1[1], co1[2], co1[3]);
    *(float4*)&S.u.s.df[2 * CC + o1][0]     = make_float4(pfx[0], pfx[1], pfx[2], pfx[3]);
    *(float4*)&S.u.s.df[2 * CC + o1 + 1][0] = make_float4(pfy[0], pfy[1], pfy[2], pfy[3]);
    __syncwarp();

    // ---- final MLP layer 1: 192 -> 64, BN folded + ReLU --------------------
    unsigned long long fXe0 = 0, fXe1 = 0, fXo0 = 0, fXo1 = 0;
    unsigned long long fYe0 = 0, fYe1 = 0, fYo0 = 0, fYo1 = 0;
    {
        const float* wrow = g_wt1a + o1;
        #pragma unroll 4
        for (int c = 0; c < 3 * CC; c += 2) {
            const ulonglong2 dE = *(const ulonglong2*)&S.u.s.df[c][0];
            const ulonglong2 dO = *(const ulonglong2*)&S.u.s.df[c + 1][0];
            const float2 wE = *(const float2*)(wrow + c * CC);
            const float2 wO = *(const float2*)(wrow + (c + 1) * CC);
            unsigned long long w;
            DUP2(w, wE.x); FMA2(fXe0, w, dE.x); FMA2(fXe1, w, dE.y);
            DUP2(w, wE.y); FMA2(fYe0, w, dE.x); FMA2(fYe1, w, dE.y);
            DUP2(w, wO.x); FMA2(fXo0, w, dO.x); FMA2(fXo1, w, dO.y);
            DUP2(w, wO.y); FMA2(fYo0, w, dO.x); FMA2(fYo1, w, dO.y);
        }
    }
    ADD2(fXe0, fXo0); ADD2(fXe1, fXo1);
    ADD2(fYe0, fYo0); ADD2(fYe1, fYo1);
    {
        float ax[4], ay[4];
        UNPK2(ax[0], ax[1], fXe0); UNPK2(ax[2], ax[3], fXe1);
        UNPK2(ay[0], ay[1], fYe0); UNPK2(ay[2], ay[3], fYe1);
        const float2 s2 = *(const float2*)(g_f1s + o1);
        const float2 b2 = *(const float2*)(g_f1b + o1);
        float hx[4], hy[4];
        #pragma unroll
        for (int p = 0; p < 4; p++) {
            hx[p] = fmaxf(fmaf(ax[p], s2.x, b2.x), 0.f);
            hy[p] = fmaxf(fmaf(ay[p], s2.y, b2.y), 0.f);
        }
        *(float4*)&S.u.s.h1[o1][0]     = make_float4(hx[0], hx[1], hx[2], hx[3]);
        *(float4*)&S.u.s.h1[o1 + 1][0] = make_float4(hy[0], hy[1], hy[2], hy[3]);
    }
    __syncwarp();

    // ---- final MLP layer 2: 64 -> 64 ---------------------------------------
    unsigned long long rXe0 = 0, rXe1 = 0, rXo0 = 0, rXo1 = 0;
    unsigned long long rYe0 = 0, rYe1 = 0, rYo0 = 0, rYo1 = 0;
    {
        const float* wrow = g_wt1b + o1;
        #pragma unroll 4
        for (int c = 0; c < CC; c += 2) {
            const ulonglong2 hE = *(const ulonglong2*)&S.u.s.h1[c][0];
            const ulonglong2 hO = *(const ulonglong2*)&S.u.s.h1[c + 1][0];
            const float2 wE = *(const float2*)(wrow + c * CC);
            const float2 wO = *(const float2*)(wrow + (c + 1) * CC);
            unsigned long long w;
            DUP2(w, wE.x); FMA2(rXe0, w, hE.x); FMA2(rXe1, w, hE.y);
            DUP2(w, wE.y); FMA2(rYe0, w, hE.x); FMA2(rYe1, w, hE.y);
            DUP2(w, wO.x); FMA2(rXo0, w, hO.x); FMA2(rXo1, w, hO.y);
            DUP2(w, wO.y); FMA2(rYo0, w, hO.x); FMA2(rYo1, w, hO.y);
        }
    }
    ADD2(rXe0, rXo0); ADD2(rXe1, rXo1);
    ADD2(rYe0, rYo0); ADD2(rYe1, rYo1);
    {
        float rx[4], ry[4];
        UNPK2(rx[0], rx[1], rXe0); UNPK2(rx[2], rx[3], rXe1);
        UNPK2(ry[0], ry[1], rYe0); UNPK2(ry[2], ry[3], rYe1);
        const float2 bo = *(const float2*)(b1b + o1);
        #pragma unroll
        for (int p = 0; p < 4; p++) {
            *(float2*)(out + ((size_t)b * NN + n0 + p) * CC + o1) =
                make_float2(rx[p] + bo.x, ry[p] + bo.y);
        }
    }
}

// ---------------------------------------------------------------------------
extern "C" void kernel_launch(void* const* d_in, const int* in_sizes, int n_in,
                              void* d_out, int out_size)
{
    (void)in_sizes; (void)n_in; (void)out_size;
    const float* pcl       = (const float*)d_in[0];
    const float* pcl_noise = (const float*)d_in[1];
    const float* feature   = (const float*)d_in[2];
    const float* w2a  = (const float*)d_in[3];
    const float* b2a  = (const float*)d_in[4];
    const float* g2a  = (const float*)d_in[5];
    const float* bt2a = (const float*)d_in[6];
    const float* w2b  = (const float*)d_in[7];
    const float* b2b  = (const float*)d_in[8];
    const float* w1a  = (const float*)d_in[9];
    const float* b1a  = (const float*)d_in[10];
    const float* g1a  = (const float*)d_in[11];
    const float* bt1a = (const float*)d_in[12];
    const float* w1b  = (const float*)d_in[13];
    const float* b1b  = (const float*)d_in[14];
    float* out = (float*)d_out;

    static int knn_smem_set = 0;
    if (!knn_smem_set) {
        cudaFuncSetAttribute(knn_kernel,
            cudaFuncAttributeMaxDynamicSharedMemorySize, MM * 16);
        knn_smem_set = 1;
    }

    prep_kernel<<<64, 256>>>(w2a, b2a, g2a, bt2a, w2b, w1a, b1a, g1a, bt1a, w1b);
    nn_part_kernel<<<dim3(NN / 128, NCHUNK, BB), 128>>>(pcl, pcl_noise);
    knn_kernel<<<dim3(MM / 32, BB), 1024, MM * 16>>>(pcl);
    fused_kernel<<<(BB * NN) / 16, 128>>>(
        pcl, pcl_noise, feature, b2b, b1b, out);
}